// round 6
// baseline (speedup 1.0000x reference)
#include <cuda_runtime.h>
#include <cstdint>

#define Nn  50000
#define Ee  800000
#define NGg 128
#define Dd  128
#define Mm  2

// ---------------- scratch ----------------
__device__ float g_tx[Nn * Dd];
__device__ float g_hA[Mm * Nn * Dd];
__device__ float g_hB[Mm * Nn * Dd];
__device__ int   g_deg[Nn];
__device__ int   g_rowptr[Nn + 1];
__device__ int   g_cursor[Nn];
__device__ int   g_col[Ee];
__device__ float g_pred[Nn];
__device__ int   g_counts[NGg];
__device__ unsigned char g_flag[Mm * Nn];
__device__ float g_hg[Mm * NGg * Dd];
__device__ int   g_amark[Mm * Nn];
__device__ int   g_alist[Mm * Nn];
__device__ int   g_naff;

// ---------------- threefry2x32 ----------------
static __host__ __device__ inline unsigned rotl32(unsigned v, int r) {
    return (v << r) | (v >> (32 - r));
}
static __host__ __device__ inline void tf2x32(unsigned k0, unsigned k1,
                                              unsigned& x0, unsigned& x1) {
    unsigned k2 = k0 ^ k1 ^ 0x1BD11BDAu;
    x0 += k0; x1 += k1;
#define TFR(r) { x0 += x1; x1 = rotl32(x1, (r)); x1 ^= x0; }
    TFR(13) TFR(15) TFR(26) TFR(6)
    x0 += k1; x1 += k2 + 1u;
    TFR(17) TFR(29) TFR(16) TFR(24)
    x0 += k2; x1 += k0 + 2u;
    TFR(13) TFR(15) TFR(26) TFR(6)
    x0 += k0; x1 += k1 + 3u;
    TFR(17) TFR(29) TFR(16) TFR(24)
    x0 += k1; x1 += k2 + 4u;
    TFR(13) TFR(15) TFR(26) TFR(6)
    x0 += k2; x1 += k0 + 5u;
#undef TFR
}

static __device__ __forceinline__ uint32_t f2tf32(float f) {
    uint32_t r;
    asm("cvt.rna.tf32.f32 %0, %1;" : "=r"(r) : "f"(f));
    return r;
}

// ---------------- gather (MLP-unrolled) ----------------
static __device__ __forceinline__ float4 gather_row(const float* __restrict__ base,
                                                    int n, int lane, float4 acc) {
    int beg = g_rowptr[n], end = g_rowptr[n + 1];
    float4 a1 = make_float4(0.f, 0.f, 0.f, 0.f);
    float4 a2 = make_float4(0.f, 0.f, 0.f, 0.f);
    float4 a3 = make_float4(0.f, 0.f, 0.f, 0.f);
    for (int b0 = beg; b0 < end; b0 += 32) {
        int lim = end - b0; if (lim > 32) lim = 32;
        int cidx = (lane < lim) ? g_col[b0 + lane] : 0;
        int j = 0;
        for (; j + 4 <= lim; j += 4) {
            int s0 = __shfl_sync(0xffffffffu, cidx, j);
            int s1 = __shfl_sync(0xffffffffu, cidx, j + 1);
            int s2 = __shfl_sync(0xffffffffu, cidx, j + 2);
            int s3 = __shfl_sync(0xffffffffu, cidx, j + 3);
            float4 v0 = *(const float4*)(base + (size_t)s0 * Dd + lane * 4);
            float4 v1 = *(const float4*)(base + (size_t)s1 * Dd + lane * 4);
            float4 v2 = *(const float4*)(base + (size_t)s2 * Dd + lane * 4);
            float4 v3 = *(const float4*)(base + (size_t)s3 * Dd + lane * 4);
            acc.x += v0.x; acc.y += v0.y; acc.z += v0.z; acc.w += v0.w;
            a1.x += v1.x; a1.y += v1.y; a1.z += v1.z; a1.w += v1.w;
            a2.x += v2.x; a2.y += v2.y; a2.z += v2.z; a2.w += v2.w;
            a3.x += v3.x; a3.y += v3.y; a3.z += v3.z; a3.w += v3.w;
        }
        for (; j < lim; j++) {
            int s0 = __shfl_sync(0xffffffffu, cidx, j);
            float4 v0 = *(const float4*)(base + (size_t)s0 * Dd + lane * 4);
            acc.x += v0.x; acc.y += v0.y; acc.z += v0.z; acc.w += v0.w;
        }
    }
    acc.x += a1.x + a2.x + a3.x;
    acc.y += a1.y + a2.y + a3.y;
    acc.z += a1.z + a2.z + a3.z;
    acc.w += a1.w + a2.w + a3.w;
    return acc;
}

// virtual x' gather for sparse patch: tx with flagged-node anchor scaling
static __device__ __forceinline__ float4 gather_xm(int n, int lane, float4 acc,
                                                   float4 av, int m) {
    int beg = g_rowptr[n], end = g_rowptr[n + 1];
    for (int b0 = beg; b0 < end; b0 += 32) {
        int lim = end - b0; if (lim > 32) lim = 32;
        int cidx = (lane < lim) ? g_col[b0 + lane] : 0;
        for (int j = 0; j < lim; j++) {
            int s = __shfl_sync(0xffffffffu, cidx, j);
            float4 v = *(const float4*)(g_tx + (size_t)s * Dd + lane * 4);
            if (g_flag[m * Nn + s]) {
                v.x = fmaf(v.x, av.x, v.x);
                v.y = fmaf(v.y, av.y, v.y);
                v.z = fmaf(v.z, av.z, v.z);
                v.w = fmaf(v.w, av.w, v.w);
            }
            acc.x += v.x; acc.y += v.y; acc.z += v.z; acc.w += v.w;
        }
    }
    return acc;
}

// ---------------- small kernels ----------------
__global__ void k_reset() {
    int i = blockIdx.x * blockDim.x + threadIdx.x;
    if (i < Mm * Nn) { g_flag[i] = 0; g_amark[i] = 0; }
    if (i < Nn) { g_deg[i] = 0; g_cursor[i] = 0; }
    if (i < Mm * NGg * Dd) g_hg[i] = 0.f;
    if (i < NGg) g_counts[i] = 0;
    if (i == 0) g_naff = 0;
}

__global__ void k_hist(const int* __restrict__ edst) {
    int e = blockIdx.x * blockDim.x + threadIdx.x;
    if (e < Ee) atomicAdd(&g_deg[edst[e]], 1);
}

__global__ void k_scan() {
    __shared__ int ss[1024];
    int tid = threadIdx.x;
    const int CH = (Nn + 1023) / 1024;
    int beg = tid * CH;
    int end = beg + CH; if (end > Nn) end = Nn;
    int s = 0;
    for (int i = beg; i < end; i++) s += g_deg[i];
    ss[tid] = s;
    __syncthreads();
    for (int off = 1; off < 1024; off <<= 1) {
        int v = (tid >= off) ? ss[tid - off] : 0;
        __syncthreads();
        ss[tid] += v;
        __syncthreads();
    }
    int base = (tid == 0) ? 0 : ss[tid - 1];
    for (int i = beg; i < end; i++) { g_rowptr[i] = base; base += g_deg[i]; }
    if (tid == 1023) g_rowptr[Nn] = ss[1023];
}

__global__ void k_fill(const int* __restrict__ esrc, const int* __restrict__ edst) {
    int e = blockIdx.x * blockDim.x + threadIdx.x;
    if (e >= Ee) return;
    int d = edst[e];
    int p = atomicAdd(&g_cursor[d], 1);
    g_col[g_rowptr[d] + p] = esrc[e];
}

__global__ void k_embed(const int* __restrict__ x_idx, const float* __restrict__ x_table,
                        const int* __restrict__ batch) {
    int idx = blockIdx.x * blockDim.x + threadIdx.x;
    if (idx >= Nn * 32) return;
    int n = idx >> 5, q = idx & 31;
    int xi = x_idx[n];
    float4 v = *(const float4*)(x_table + (size_t)xi * Dd + q * 4);
    *(float4*)(g_tx + (size_t)n * Dd + q * 4) = v;
    if (q == 0) atomicAdd(&g_counts[batch[n]], 1);
}

// ---------------- mma common ----------------
#define SW_STR 136
#define SI_STR 132
static __device__ __forceinline__ void mma_tf32(float* c, const uint32_t* a, const uint32_t* b) {
    asm volatile(
        "mma.sync.aligned.m16n8k8.row.col.f32.tf32.tf32.f32 "
        "{%0,%1,%2,%3}, {%4,%5,%6,%7}, {%8,%9}, {%0,%1,%2,%3};"
        : "+f"(c[0]), "+f"(c[1]), "+f"(c[2]), "+f"(c[3])
        : "r"(a[0]), "r"(a[1]), "r"(a[2]), "r"(a[3]), "r"(b[0]), "r"(b[1]));
}

// ---------------- 3xTF32 (fp32-accurate) pass-1 kernel ----------------
// mode 0 = L1: in tx + gather, relu -> dual-write g_hA[m=0] and g_hA[m=1]
// mode 1 = L2: in g_hA(m0) + gather, relu -> pred = relu·Wd + bd
// mode 2 = sparse patch: rows g_alist, virtual x' (tx + flag scaling), relu -> g_hA[row]
#define SMEM_MMA3 ((2 * 128 * SW_STR + 2 * 64 * SI_STR + 128 + 64) * 4)
__global__ __launch_bounds__(256) void k_mma3(
    int mode,
    const float* __restrict__ W, const float* __restrict__ bias,
    const float* __restrict__ Wd, const float* __restrict__ bd,
    const float* __restrict__ anchor_table, int nrows, int sparse)
{
    extern __shared__ float sm[];
    float* sWhi = sm;
    float* sWlo = sWhi + 128 * SW_STR;
    float* sInhi = sWlo + 128 * SW_STR;
    float* sInlo = sInhi + 64 * SI_STR;
    float* sWd = sInlo + 64 * SI_STR;
    int* sRow = (int*)(sWd + 128);
    int t = threadIdx.x, lane = t & 31, wid = t >> 5;
    int gid = lane >> 2, tig = lane & 3;
    int wr = wid >> 2, wc = wid & 3;

    for (int idx = t; idx < 16384; idx += 256) {
        int k = idx >> 7, c = idx & 127;
        float w = W[idx];
        uint32_t hb = f2tf32(w);
        float lo = w - __uint_as_float(hb);
        sWhi[k * SW_STR + c] = __uint_as_float(hb);
        sWlo[k * SW_STR + c] = __uint_as_float(f2tf32(lo));
    }
    if (mode == 1 && t < 128) sWd[t] = Wd[t];
    int total = sparse ? g_naff : nrows;

    for (int tile = blockIdx.x; tile * 64 < total; tile += gridDim.x) {
        if (t < 64) {
            int idx = tile * 64 + t;
            sRow[t] = (idx < total) ? (sparse ? g_alist[idx] : idx) : -1;
        }
        __syncthreads();

        for (int rr = wid; rr < 64; rr += 8) {
            int grow = sRow[rr];
            float4 acc = make_float4(0.f, 0.f, 0.f, 0.f);
            if (grow >= 0) {
                if (mode == 1) {
                    acc = *(const float4*)(g_hA + (size_t)grow * Dd + lane * 4);
                    acc = gather_row(g_hA, grow, lane, acc);
                } else if (mode == 0) {
                    acc = *(const float4*)(g_tx + (size_t)grow * Dd + lane * 4);
                    acc = gather_row(g_tx, grow, lane, acc);
                } else {
                    int m = grow / Nn, n = grow - m * Nn;
                    float4 av = *(const float4*)(anchor_table + Dd + lane * 4);
                    acc = *(const float4*)(g_tx + (size_t)n * Dd + lane * 4);
                    if (g_flag[grow]) {
                        acc.x = fmaf(acc.x, av.x, acc.x);
                        acc.y = fmaf(acc.y, av.y, acc.y);
                        acc.z = fmaf(acc.z, av.z, acc.z);
                        acc.w = fmaf(acc.w, av.w, acc.w);
                    }
                    acc = gather_xm(n, lane, acc, av, m);
                }
            }
            float* dh = &sInhi[rr * SI_STR + lane * 4];
            float* dl = &sInlo[rr * SI_STR + lane * 4];
            uint32_t hx = f2tf32(acc.x), hy = f2tf32(acc.y);
            uint32_t hz = f2tf32(acc.z), hw = f2tf32(acc.w);
            dh[0] = __uint_as_float(hx); dh[1] = __uint_as_float(hy);
            dh[2] = __uint_as_float(hz); dh[3] = __uint_as_float(hw);
            dl[0] = __uint_as_float(f2tf32(acc.x - __uint_as_float(hx)));
            dl[1] = __uint_as_float(f2tf32(acc.y - __uint_as_float(hy)));
            dl[2] = __uint_as_float(f2tf32(acc.z - __uint_as_float(hz)));
            dl[3] = __uint_as_float(f2tf32(acc.w - __uint_as_float(hw)));
        }
        __syncthreads();

        float c_[2][4][4];
#pragma unroll
        for (int mt = 0; mt < 2; mt++)
#pragma unroll
            for (int nt = 0; nt < 4; nt++)
#pragma unroll
                for (int q = 0; q < 4; q++) c_[mt][nt][q] = 0.f;

#pragma unroll 2
        for (int ks = 0; ks < 16; ks++) {
            int k0 = ks * 8;
            uint32_t ah[2][4], al[2][4], bh[4][2], bl[4][2];
#pragma unroll
            for (int mt = 0; mt < 2; mt++) {
                int off = (wr * 32 + mt * 16 + gid) * SI_STR + k0 + tig;
                ah[mt][0] = __float_as_uint(sInhi[off]);
                ah[mt][1] = __float_as_uint(sInhi[off + 8 * SI_STR]);
                ah[mt][2] = __float_as_uint(sInhi[off + 4]);
                ah[mt][3] = __float_as_uint(sInhi[off + 8 * SI_STR + 4]);
                al[mt][0] = __float_as_uint(sInlo[off]);
                al[mt][1] = __float_as_uint(sInlo[off + 8 * SI_STR]);
                al[mt][2] = __float_as_uint(sInlo[off + 4]);
                al[mt][3] = __float_as_uint(sInlo[off + 8 * SI_STR + 4]);
            }
#pragma unroll
            for (int nt = 0; nt < 4; nt++) {
                int off = (k0 + tig) * SW_STR + wc * 32 + nt * 8 + gid;
                bh[nt][0] = __float_as_uint(sWhi[off]);
                bh[nt][1] = __float_as_uint(sWhi[off + 4 * SW_STR]);
                bl[nt][0] = __float_as_uint(sWlo[off]);
                bl[nt][1] = __float_as_uint(sWlo[off + 4 * SW_STR]);
            }
#pragma unroll
            for (int mt = 0; mt < 2; mt++)
#pragma unroll
                for (int nt = 0; nt < 4; nt++) {
                    mma_tf32(c_[mt][nt], ah[mt], bl[nt]);
                    mma_tf32(c_[mt][nt], al[mt], bh[nt]);
                    mma_tf32(c_[mt][nt], ah[mt], bh[nt]);
                }
        }
        __syncthreads();

        // stage relu(acc + bias) into sInhi (fp32)
#pragma unroll
        for (int mt = 0; mt < 2; mt++) {
#pragma unroll
            for (int nt = 0; nt < 4; nt++) {
                int col = wc * 32 + nt * 8 + tig * 2;
                int row = wr * 32 + mt * 16 + gid;
                float b0 = bias[col], b1 = bias[col + 1];
                sInhi[row * SI_STR + col]           = fmaxf(c_[mt][nt][0] + b0, 0.f);
                sInhi[row * SI_STR + col + 1]       = fmaxf(c_[mt][nt][1] + b1, 0.f);
                sInhi[(row + 8) * SI_STR + col]     = fmaxf(c_[mt][nt][2] + b0, 0.f);
                sInhi[(row + 8) * SI_STR + col + 1] = fmaxf(c_[mt][nt][3] + b1, 0.f);
            }
        }
        __syncthreads();

        if (mode == 1) {
            float4 wd = *(const float4*)(sWd + lane * 4);
#pragma unroll
            for (int r = 0; r < 8; r++) {
                int rr = wid * 8 + r;
                int grow = sRow[rr];
                float4 v = *(const float4*)(sInhi + rr * SI_STR + lane * 4);
                float p = v.x * wd.x + v.y * wd.y + v.z * wd.z + v.w * wd.w;
#pragma unroll
                for (int o = 16; o > 0; o >>= 1) p += __shfl_xor_sync(0xffffffffu, p, o);
                if (lane == 0 && grow >= 0) g_pred[grow] = p + bd[0];
            }
        } else {
            for (int idx = t; idx < 2048; idx += 256) {
                int rr = idx >> 5, q = idx & 31;
                int grow = sRow[rr];
                if (grow < 0) continue;
                float4 v = *(const float4*)(sInhi + rr * SI_STR + q * 4);
                *(float4*)(g_hA + (size_t)grow * Dd + q * 4) = v;
                if (mode == 0) *(float4*)(g_hA + (size_t)(grow + Nn) * Dd + q * 4) = v;
            }
        }
        __syncthreads();
    }
}

// ---------------- 1xTF32 pass-2 kernel (unchanged layout from R5) ----------------
#define SMEM_MMA ((128 * SW_STR + 64 * SI_STR) * 4 + 64 * 4)
__global__ __launch_bounds__(256) void k_mma(
    int gather, int pool, int insel,
    const float* __restrict__ W, const float* __restrict__ bias,
    const int* __restrict__ batch, int nrows)
{
    extern __shared__ float sm[];
    float* sW = sm;
    float* sIn = sm + 128 * SW_STR;
    int* sRow = (int*)(sIn + 64 * SI_STR);
    const float* in = (insel == 2) ? g_hA : g_hB;
    int t = threadIdx.x, lane = t & 31, wid = t >> 5;
    int gid = lane >> 2, tig = lane & 3;
    int wr = wid >> 2, wc = wid & 3;

    for (int idx = t; idx < 16384; idx += 256) {
        int k = idx >> 7, c = idx & 127;
        sW[k * SW_STR + c] = __uint_as_float(f2tf32(W[idx]));
    }

    int ntile = (nrows + 63) >> 6;
    for (int tile = blockIdx.x; tile < ntile; tile += gridDim.x) {
        if (t < 64) {
            int idx = tile * 64 + t;
            sRow[t] = (idx < nrows) ? idx : -1;
        }
        __syncthreads();

        for (int rr = wid; rr < 64; rr += 8) {
            int grow = sRow[rr];
            float4 acc = make_float4(0.f, 0.f, 0.f, 0.f);
            if (grow >= 0) {
                int m = grow / Nn, n = grow - m * Nn;
                const float* base = in + (size_t)m * Nn * Dd;
                acc = *(const float4*)(base + (size_t)n * Dd + lane * 4);
                if (gather) acc = gather_row(base, n, lane, acc);
            }
            float* d = &sIn[rr * SI_STR + lane * 4];
            d[0] = __uint_as_float(f2tf32(acc.x));
            d[1] = __uint_as_float(f2tf32(acc.y));
            d[2] = __uint_as_float(f2tf32(acc.z));
            d[3] = __uint_as_float(f2tf32(acc.w));
        }
        __syncthreads();

        float c_[2][4][4];
#pragma unroll
        for (int mt = 0; mt < 2; mt++)
#pragma unroll
            for (int nt = 0; nt < 4; nt++)
#pragma unroll
                for (int q = 0; q < 4; q++) c_[mt][nt][q] = 0.f;

#pragma unroll 4
        for (int ks = 0; ks < 16; ks++) {
            int k0 = ks * 8;
            uint32_t a[2][4], b[4][2];
#pragma unroll
            for (int mt = 0; mt < 2; mt++) {
                const float* Ap = sIn + (wr * 32 + mt * 16 + gid) * SI_STR + k0 + tig;
                a[mt][0] = __float_as_uint(Ap[0]);
                a[mt][1] = __float_as_uint(Ap[8 * SI_STR]);
                a[mt][2] = __float_as_uint(Ap[4]);
                a[mt][3] = __float_as_uint(Ap[8 * SI_STR + 4]);
            }
#pragma unroll
            for (int nt = 0; nt < 4; nt++) {
                const float* Bp = sW + (k0 + tig) * SW_STR + wc * 32 + nt * 8 + gid;
                b[nt][0] = __float_as_uint(Bp[0]);
                b[nt][1] = __float_as_uint(Bp[4 * SW_STR]);
            }
#pragma unroll
            for (int mt = 0; mt < 2; mt++)
#pragma unroll
                for (int nt = 0; nt < 4; nt++)
                    mma_tf32(c_[mt][nt], a[mt], b[nt]);
        }
        __syncthreads();

#pragma unroll
        for (int mt = 0; mt < 2; mt++) {
#pragma unroll
            for (int nt = 0; nt < 4; nt++) {
                int col = wc * 32 + nt * 8 + tig * 2;
                int row = wr * 32 + mt * 16 + gid;
                float b0 = bias[col], b1 = bias[col + 1];
                sIn[row * SI_STR + col]           = fmaxf(c_[mt][nt][0] + b0, 0.f);
                sIn[row * SI_STR + col + 1]       = fmaxf(c_[mt][nt][1] + b1, 0.f);
                sIn[(row + 8) * SI_STR + col]     = fmaxf(c_[mt][nt][2] + b0, 0.f);
                sIn[(row + 8) * SI_STR + col + 1] = fmaxf(c_[mt][nt][3] + b1, 0.f);
            }
        }
        __syncthreads();

        if (pool) {
            int col = t & 127, half = t >> 7;
            float s = 0.f; int cur = -1;
            for (int rr = half * 32; rr < half * 32 + 32; rr++) {
                int grow = sRow[rr]; if (grow < 0) continue;
                int m = grow / Nn;
                int key = m * NGg + batch[grow - m * Nn];
                if (key != cur) {
                    if (cur >= 0) atomicAdd(&g_hg[(size_t)cur * Dd + col], s);
                    cur = key; s = 0.f;
                }
                s += sIn[rr * SI_STR + col];
            }
            if (cur >= 0) atomicAdd(&g_hg[(size_t)cur * Dd + col], s);
        } else {
            for (int idx = t; idx < 2048; idx += 256) {
                int rr = idx >> 5, q = idx & 31;
                int grow = sRow[rr];
                if (grow < 0) continue;
                *(float4*)(g_hB + (size_t)grow * Dd + q * 4) =
                    *(float4*)(sIn + rr * SI_STR + q * 4);
            }
        }
        __syncthreads();
    }
}

// ---------------- fused per-graph sampling ----------------
static __device__ __forceinline__ float score_fn(int n, int m, float mx, float ssum,
                                                 unsigned fk0, unsigned fk1) {
    float e = expf(g_pred[n] - mx);
    float p = e / ssum;
    float lp = logf(p + 1e-15f);
    unsigned x0 = 0u, x1 = (unsigned)(m * Nn + n);
    tf2x32(fk0, fk1, x0, x1);
    float u = __uint_as_float((x1 >> 9) | 0x3F800000u) - 1.0f;
    u = fmaxf(u, 0.0f);
    float gum = -logf(-logf(u + 1e-12f) + 1e-12f);
    return lp + gum;
}

__global__ void k_sample(const int* __restrict__ batch, unsigned fk0, unsigned fk1) {
    __shared__ float fb[8];
    __shared__ int ib[8];
    __shared__ int sSE[2];
    __shared__ float sMx, sSum, sBest;
    int g = blockIdx.x, t = threadIdx.x, lane = t & 31, wid = t >> 5;
    if (t < 2) {
        int tgt = g + t;
        int lo = 0, hi = Nn;
        while (lo < hi) { int mid = (lo + hi) >> 1; if (batch[mid] < tgt) lo = mid + 1; else hi = mid; }
        sSE[t] = lo;
    }
    __syncthreads();
    int s0 = sSE[0], s1 = sSE[1];

    float mx = -3.4e38f;
    for (int n = s0 + t; n < s1; n += 256) mx = fmaxf(mx, g_pred[n]);
#pragma unroll
    for (int o = 16; o > 0; o >>= 1) mx = fmaxf(mx, __shfl_xor_sync(0xffffffffu, mx, o));
    if (lane == 0) fb[wid] = mx;
    __syncthreads();
    if (t == 0) { float x = fb[0]; for (int i = 1; i < 8; i++) x = fmaxf(x, fb[i]); sMx = x; }
    __syncthreads();
    float gmx = sMx;

    float sm = 0.f;
    for (int n = s0 + t; n < s1; n += 256) sm += expf(g_pred[n] - gmx);
#pragma unroll
    for (int o = 16; o > 0; o >>= 1) sm += __shfl_xor_sync(0xffffffffu, sm, o);
    if (lane == 0) fb[wid] = sm;
    __syncthreads();
    if (t == 0) { float x = 0.f; for (int i = 0; i < 8; i++) x += fb[i]; sSum = x; }
    __syncthreads();
    float gsum = sSum;

    for (int m = 0; m < Mm; m++) {
        float best = -3.4e38f;
        for (int n = s0 + t; n < s1; n += 256)
            best = fmaxf(best, score_fn(n, m, gmx, gsum, fk0, fk1));
#pragma unroll
        for (int o = 16; o > 0; o >>= 1) best = fmaxf(best, __shfl_xor_sync(0xffffffffu, best, o));
        if (lane == 0) fb[wid] = best;
        __syncthreads();
        if (t == 0) { float x = fb[0]; for (int i = 1; i < 8; i++) x = fmaxf(x, fb[i]); sBest = x; }
        __syncthreads();
        float gb = sBest;
        __syncthreads();

        int cand = Nn;
        for (int n = s0 + t; n < s1; n += 256)
            if (score_fn(n, m, gmx, gsum, fk0, fk1) >= gb) cand = min(cand, n);
#pragma unroll
        for (int o = 16; o > 0; o >>= 1) cand = min(cand, __shfl_xor_sync(0xffffffffu, cand, o));
        if (lane == 0) ib[wid] = cand;
        __syncthreads();
        if (t == 0) {
            int x = ib[0]; for (int i = 1; i < 8; i++) x = min(x, ib[i]);
            if (x < Nn) {
                g_flag[m * Nn + x] = 1;
                if (atomicExch(&g_amark[m * Nn + x], 1) == 0) {
                    int p = atomicAdd(&g_naff, 1);
                    g_alist[p] = m * Nn + x;
                }
            }
        }
        __syncthreads();
    }
}

// single-pass mark: rows whose L1 aggregation changes per m
__global__ void k_mark(const int* __restrict__ esrc, const int* __restrict__ edst) {
    int e = blockIdx.x * blockDim.x + threadIdx.x;
    if (e >= Ee) return;
    int s = esrc[e];
    unsigned char f0 = g_flag[s];
    unsigned char f1 = g_flag[Nn + s];
    if (!(f0 | f1)) return;
    int d = edst[e];
    if (f0 && atomicExch(&g_amark[d], 1) == 0) {
        int p = atomicAdd(&g_naff, 1);
        g_alist[p] = d;
    }
    if (f1 && atomicExch(&g_amark[Nn + d], 1) == 0) {
        int p = atomicAdd(&g_naff, 1);
        g_alist[p] = Nn + d;
    }
}

__global__ void k_final(const float* __restrict__ Wp, const float* __restrict__ bp,
                        float* __restrict__ out) {
    __shared__ float red[128];
    int g = blockIdx.x, t = threadIdx.x;
    int c = g_counts[g]; if (c < 1) c = 1;
    float inv = 1.0f / (float)c;
    float hsum = (g_hg[(size_t)g * Dd + t] + g_hg[((size_t)NGg + g) * Dd + t]) * inv;
    for (int tt = 0; tt < 10; tt++) {
        red[t] = hsum * Wp[t * 10 + tt];
        __syncthreads();
        for (int off = 64; off > 0; off >>= 1) {
            if (t < off) red[t] += red[t + off];
            __syncthreads();
        }
        if (t == 0) out[g * 10 + tt] = red[0] * 0.5f + bp[tt];
        __syncthreads();
    }
}

// ---------------- launch ----------------
static inline int cdiv(int a, int b) { return (a + b - 1) / b; }

extern "C" void kernel_launch(void* const* d_in, const int* in_sizes, int n_in,
                              void* d_out, int out_size) {
    const int*   x_idx        = (const int*)d_in[0];
    const int*   esrc         = (const int*)d_in[1];
    const int*   edst         = (const int*)d_in[2];
    const int*   batch        = (const int*)d_in[3];
    const float* x_table      = (const float*)d_in[4];
    const float* anchor_table = (const float*)d_in[5];
    const float* Wg           = (const float*)d_in[6];
    const float* bg           = (const float*)d_in[7];
    const float* Wn           = (const float*)d_in[8];
    const float* bn           = (const float*)d_in[9];
    const float* Wd           = (const float*)d_in[10];
    const float* bd           = (const float*)d_in[11];
    const float* Wp           = (const float*)d_in[12];
    const float* bp           = (const float*)d_in[13];
    float* out = (float*)d_out;

    unsigned fk0 = 0u, fk1 = 1u;
    tf2x32(0u, 1u, fk0, fk1);

    cudaFuncSetAttribute(k_mma, cudaFuncAttributeMaxDynamicSharedMemorySize, SMEM_MMA);
    cudaFuncSetAttribute(k_mma3, cudaFuncAttributeMaxDynamicSharedMemorySize, SMEM_MMA3);

    // setup
    k_reset<<<cdiv(Mm * Nn, 256), 256>>>();
    k_hist<<<cdiv(Ee, 256), 256>>>(edst);
    k_scan<<<1, 1024>>>();
    k_fill<<<cdiv(Ee, 256), 256>>>(esrc, edst);
    k_embed<<<cdiv(Nn * 32, 256), 256>>>(x_idx, x_table, batch);

    // pass1 (3xTF32 ~ fp32): L1 dual-write g_hA; L2 fused pred epilogue
    k_mma3<<<148, 256, SMEM_MMA3>>>(0, Wg, bg, nullptr, nullptr, anchor_table, Nn, 0);
    k_mma3<<<148, 256, SMEM_MMA3>>>(1, Wg + Dd * Dd, bg + Dd, Wd, bd, anchor_table, Nn, 0);

    // anchor sampling + affected-row marking
    k_sample<<<NGg, 256>>>(batch, fk0, fk1);
    k_mark<<<cdiv(Ee, 256), 256>>>(esrc, edst);

    // pass2 L1: sparse patch, virtual x' computed on the fly (3xTF32)
    k_mma3<<<148, 256, SMEM_MMA3>>>(2, Wg, bg, nullptr, nullptr, anchor_table, 0, 1);

    // pass2 L2 (1xTF32): g_hA -> g_hB
    k_mma<<<296, 256, SMEM_MMA>>>(1, 0, 2, Wg + Dd * Dd, bg + Dd, batch, Mm * Nn);
    // node MLP + pooled epilogue (1xTF32): g_hB -> g_hg
    k_mma<<<296, 256, SMEM_MMA>>>(0, 1, 3, Wn, bn, batch, Mm * Nn);

    // final projection + mean over m
    k_final<<<NGg, 128>>>(Wp, bp, out);
}

// round 7
// speedup vs baseline: 1.5791x; 1.5791x over previous
#include <cuda_runtime.h>
#include <cstdint>

#define Nn  50000
#define Ee  800000
#define NGg 128
#define Dd  128
#define Mm  2

// ---------------- scratch ----------------
__device__ float g_tx[Nn * Dd];
__device__ float g_hA[Mm * Nn * Dd];
__device__ float g_hB[Mm * Nn * Dd];
__device__ int   g_deg[Nn];
__device__ int   g_rowptr[Nn + 1];
__device__ int   g_cursor[Nn];
__device__ int   g_col[Ee];
__device__ float g_pred[Nn];
__device__ int   g_counts[NGg];
__device__ unsigned char g_flag[Mm * Nn];
__device__ float g_hg[Mm * NGg * Dd];
__device__ int   g_amark[Mm * Nn];
__device__ int   g_alist[Mm * Nn];
__device__ int   g_naff;

// ---------------- threefry2x32 ----------------
static __host__ __device__ inline unsigned rotl32(unsigned v, int r) {
    return (v << r) | (v >> (32 - r));
}
static __host__ __device__ inline void tf2x32(unsigned k0, unsigned k1,
                                              unsigned& x0, unsigned& x1) {
    unsigned k2 = k0 ^ k1 ^ 0x1BD11BDAu;
    x0 += k0; x1 += k1;
#define TFR(r) { x0 += x1; x1 = rotl32(x1, (r)); x1 ^= x0; }
    TFR(13) TFR(15) TFR(26) TFR(6)
    x0 += k1; x1 += k2 + 1u;
    TFR(17) TFR(29) TFR(16) TFR(24)
    x0 += k2; x1 += k0 + 2u;
    TFR(13) TFR(15) TFR(26) TFR(6)
    x0 += k0; x1 += k1 + 3u;
    TFR(17) TFR(29) TFR(16) TFR(24)
    x0 += k1; x1 += k2 + 4u;
    TFR(13) TFR(15) TFR(26) TFR(6)
    x0 += k2; x1 += k0 + 5u;
#undef TFR
}

static __device__ __forceinline__ uint32_t f2tf32(float f) {
    uint32_t r;
    asm("cvt.rna.tf32.f32 %0, %1;" : "=r"(r) : "f"(f));
    return r;
}

// ---------------- gather (MLP-unrolled) ----------------
static __device__ __forceinline__ float4 gather_row(const float* __restrict__ base,
                                                    int n, int lane, float4 acc) {
    int beg = g_rowptr[n], end = g_rowptr[n + 1];
    float4 a1 = make_float4(0.f, 0.f, 0.f, 0.f);
    float4 a2 = make_float4(0.f, 0.f, 0.f, 0.f);
    float4 a3 = make_float4(0.f, 0.f, 0.f, 0.f);
    for (int b0 = beg; b0 < end; b0 += 32) {
        int lim = end - b0; if (lim > 32) lim = 32;
        int cidx = (lane < lim) ? g_col[b0 + lane] : 0;
        int j = 0;
        for (; j + 4 <= lim; j += 4) {
            int s0 = __shfl_sync(0xffffffffu, cidx, j);
            int s1 = __shfl_sync(0xffffffffu, cidx, j + 1);
            int s2 = __shfl_sync(0xffffffffu, cidx, j + 2);
            int s3 = __shfl_sync(0xffffffffu, cidx, j + 3);
            float4 v0 = *(const float4*)(base + (size_t)s0 * Dd + lane * 4);
            float4 v1 = *(const float4*)(base + (size_t)s1 * Dd + lane * 4);
            float4 v2 = *(const float4*)(base + (size_t)s2 * Dd + lane * 4);
            float4 v3 = *(const float4*)(base + (size_t)s3 * Dd + lane * 4);
            acc.x += v0.x; acc.y += v0.y; acc.z += v0.z; acc.w += v0.w;
            a1.x += v1.x; a1.y += v1.y; a1.z += v1.z; a1.w += v1.w;
            a2.x += v2.x; a2.y += v2.y; a2.z += v2.z; a2.w += v2.w;
            a3.x += v3.x; a3.y += v3.y; a3.z += v3.z; a3.w += v3.w;
        }
        for (; j < lim; j++) {
            int s0 = __shfl_sync(0xffffffffu, cidx, j);
            float4 v0 = *(const float4*)(base + (size_t)s0 * Dd + lane * 4);
            acc.x += v0.x; acc.y += v0.y; acc.z += v0.z; acc.w += v0.w;
        }
    }
    acc.x += a1.x + a2.x + a3.x;
    acc.y += a1.y + a2.y + a3.y;
    acc.z += a1.z + a2.z + a3.z;
    acc.w += a1.w + a2.w + a3.w;
    return acc;
}

// virtual x' gather: tx with flag-predicated anchor scaling (pass-2 input, never materialized)
static __device__ __forceinline__ float4 gather_xm(int n, int lane, float4 acc,
                                                   float4 av, int m) {
    int beg = g_rowptr[n], end = g_rowptr[n + 1];
    for (int b0 = beg; b0 < end; b0 += 32) {
        int lim = end - b0; if (lim > 32) lim = 32;
        int cidx = (lane < lim) ? g_col[b0 + lane] : 0;
        for (int j = 0; j < lim; j++) {
            int s = __shfl_sync(0xffffffffu, cidx, j);
            float4 v = *(const float4*)(g_tx + (size_t)s * Dd + lane * 4);
            if (g_flag[m * Nn + s]) {
                v.x = fmaf(v.x, av.x, v.x);
                v.y = fmaf(v.y, av.y, v.y);
                v.z = fmaf(v.z, av.z, v.z);
                v.w = fmaf(v.w, av.w, v.w);
            }
            acc.x += v.x; acc.y += v.y; acc.z += v.z; acc.w += v.w;
        }
    }
    return acc;
}

// ---------------- small kernels ----------------
__global__ void k_reset() {
    int i = blockIdx.x * blockDim.x + threadIdx.x;
    if (i < Mm * Nn) { g_flag[i] = 0; g_amark[i] = 0; }
    if (i < Nn) { g_deg[i] = 0; g_cursor[i] = 0; }
    if (i < Mm * NGg * Dd) g_hg[i] = 0.f;
    if (i < NGg) g_counts[i] = 0;
    if (i == 0) g_naff = 0;
}

__global__ void k_hist(const int* __restrict__ edst) {
    int e = blockIdx.x * blockDim.x + threadIdx.x;
    if (e < Ee) atomicAdd(&g_deg[edst[e]], 1);
}

__global__ void k_scan() {
    __shared__ int ss[1024];
    int tid = threadIdx.x;
    const int CH = (Nn + 1023) / 1024;
    int beg = tid * CH;
    int end = beg + CH; if (end > Nn) end = Nn;
    int s = 0;
    for (int i = beg; i < end; i++) s += g_deg[i];
    ss[tid] = s;
    __syncthreads();
    for (int off = 1; off < 1024; off <<= 1) {
        int v = (tid >= off) ? ss[tid - off] : 0;
        __syncthreads();
        ss[tid] += v;
        __syncthreads();
    }
    int base = (tid == 0) ? 0 : ss[tid - 1];
    for (int i = beg; i < end; i++) { g_rowptr[i] = base; base += g_deg[i]; }
    if (tid == 1023) g_rowptr[Nn] = ss[1023];
}

__global__ void k_fill(const int* __restrict__ esrc, const int* __restrict__ edst) {
    int e = blockIdx.x * blockDim.x + threadIdx.x;
    if (e >= Ee) return;
    int d = edst[e];
    int p = atomicAdd(&g_cursor[d], 1);
    g_col[g_rowptr[d] + p] = esrc[e];
}

__global__ void k_embed(const int* __restrict__ x_idx, const float* __restrict__ x_table,
                        const int* __restrict__ batch) {
    int idx = blockIdx.x * blockDim.x + threadIdx.x;
    if (idx >= Nn * 32) return;
    int n = idx >> 5, q = idx & 31;
    int xi = x_idx[n];
    float4 v = *(const float4*)(x_table + (size_t)xi * Dd + q * 4);
    *(float4*)(g_tx + (size_t)n * Dd + q * 4) = v;
    if (q == 0) atomicAdd(&g_counts[batch[n]], 1);
}

// ---------------- fp32 fused gather+GEMM (pass 1 exact + sparse patch) ----------------
// insel: 0=g_tx  1=virtual x' (tx + flag scaling)  2=g_hA
// mode : 0 = relu out, dual-write both m slices of g_hA
//        1 = pred epilogue: g_pred[row] = relu(h)·Wd + bd
//        2 = relu out to g_hA (sparse patch)
__global__ __launch_bounds__(256) void k_fused(
    int insel, int mode,
    const float* __restrict__ W, const float* __restrict__ bias,
    const float* __restrict__ Wd, const float* __restrict__ bd,
    const float* __restrict__ anchor_table, int nrows, int sparse)
{
    __shared__ float sIn[64 * 129];
    __shared__ float sW[16 * 128];
    __shared__ int sRow[64];
    int t = threadIdx.x, lane = t & 31, wid = t >> 5;
    int rg = t >> 4, cg = t & 15;
    int total = sparse ? g_naff : nrows;

    for (int tile = blockIdx.x; tile * 64 < total; tile += gridDim.x) {
        if (t < 64) {
            int idx = tile * 64 + t;
            sRow[t] = (idx < total) ? (sparse ? g_alist[idx] : idx) : -1;
        }
        __syncthreads();

        for (int rr = wid; rr < 64; rr += 8) {
            int grow = sRow[rr];
            float4 acc = make_float4(0.f, 0.f, 0.f, 0.f);
            if (grow >= 0) {
                if (insel == 0) {
                    acc = *(const float4*)(g_tx + (size_t)grow * Dd + lane * 4);
                    acc = gather_row(g_tx, grow, lane, acc);
                } else if (insel == 2) {
                    acc = *(const float4*)(g_hA + (size_t)grow * Dd + lane * 4);
                    acc = gather_row(g_hA, grow, lane, acc);
                } else {
                    int m = grow / Nn, n = grow - m * Nn;
                    float4 av = *(const float4*)(anchor_table + Dd + lane * 4);
                    acc = *(const float4*)(g_tx + (size_t)n * Dd + lane * 4);
                    if (g_flag[grow]) {
                        acc.x = fmaf(acc.x, av.x, acc.x);
                        acc.y = fmaf(acc.y, av.y, acc.y);
                        acc.z = fmaf(acc.z, av.z, acc.z);
                        acc.w = fmaf(acc.w, av.w, acc.w);
                    }
                    acc = gather_xm(n, lane, acc, av, m);
                }
            }
            float* d = &sIn[rr * 129 + lane * 4];
            d[0] = acc.x; d[1] = acc.y; d[2] = acc.z; d[3] = acc.w;
        }
        __syncthreads();

        float acc[4][8];
#pragma unroll
        for (int r = 0; r < 4; r++)
#pragma unroll
            for (int j = 0; j < 8; j++) acc[r][j] = 0.f;

        for (int kc = 0; kc < 8; kc++) {
            const float4* Ws = (const float4*)(W + kc * 16 * 128);
            ((float4*)sW)[t] = Ws[t];
            ((float4*)sW)[t + 256] = Ws[t + 256];
            __syncthreads();
#pragma unroll
            for (int kk = 0; kk < 16; kk++) {
                float a[4], w[8];
#pragma unroll
                for (int r = 0; r < 4; r++) a[r] = sIn[(rg + 16 * r) * 129 + kc * 16 + kk];
#pragma unroll
                for (int j = 0; j < 8; j++) w[j] = sW[kk * 128 + cg + 16 * j];
#pragma unroll
                for (int r = 0; r < 4; r++)
#pragma unroll
                    for (int j = 0; j < 8; j++) acc[r][j] = fmaf(a[r], w[j], acc[r][j]);
            }
            __syncthreads();
        }

        if (mode == 1) {
#pragma unroll
            for (int r = 0; r < 4; r++) {
                int grow = sRow[rg + 16 * r];
                float p = 0.f;
#pragma unroll
                for (int j = 0; j < 8; j++) {
                    float v = fmaxf(acc[r][j] + bias[cg + 16 * j], 0.f);
                    p = fmaf(v, Wd[cg + 16 * j], p);
                }
#pragma unroll
                for (int o = 8; o > 0; o >>= 1) p += __shfl_xor_sync(0xffffffffu, p, o);
                if (cg == 0 && grow >= 0) g_pred[grow] = p + bd[0];
            }
        } else {
#pragma unroll
            for (int r = 0; r < 4; r++) {
                int rr = rg + 16 * r; int grow = sRow[rr];
                if (grow < 0) continue;
#pragma unroll
                for (int j = 0; j < 8; j++) {
                    float v = fmaxf(acc[r][j] + bias[cg + 16 * j], 0.f);
                    g_hA[(size_t)grow * Dd + cg + 16 * j] = v;
                    if (mode == 0) g_hA[(size_t)(grow + Nn) * Dd + cg + 16 * j] = v;
                }
            }
        }
        __syncthreads();
    }
}

// ---------------- tf32 mma.sync GEMM, 512 threads (16 warps) ----------------
// 64 rows x 128 cols per tile; warp grid 4x4, each warp 16 rows x 32 cols.
#define SW_STR 136
#define SI_STR 132
#define SMEM_MMA ((128 * SW_STR + 64 * SI_STR) * 4 + 64 * 4)

static __device__ __forceinline__ void mma_tf32(float* c, const uint32_t* a, const uint32_t* b) {
    asm volatile(
        "mma.sync.aligned.m16n8k8.row.col.f32.tf32.tf32.f32 "
        "{%0,%1,%2,%3}, {%4,%5,%6,%7}, {%8,%9}, {%0,%1,%2,%3};"
        : "+f"(c[0]), "+f"(c[1]), "+f"(c[2]), "+f"(c[3])
        : "r"(a[0]), "r"(a[1]), "r"(a[2]), "r"(a[3]), "r"(b[0]), "r"(b[1]));
}

__global__ __launch_bounds__(512) void k_mma(
    int gather, int pool, int insel,
    const float* __restrict__ W, const float* __restrict__ bias,
    const int* __restrict__ batch, int nrows)
{
    extern __shared__ float sm[];
    float* sW = sm;
    float* sIn = sm + 128 * SW_STR;
    int* sRow = (int*)(sIn + 64 * SI_STR);
    const float* in = (insel == 2) ? g_hA : g_hB;
    int t = threadIdx.x, lane = t & 31, wid = t >> 5;
    int gid = lane >> 2, tig = lane & 3;
    int wr = wid >> 2, wc = wid & 3;   // warp grid 4 x 4 (16 rows x 32 cols each)

    for (int idx = t; idx < 16384; idx += 512) {
        int k = idx >> 7, c = idx & 127;
        sW[k * SW_STR + c] = __uint_as_float(f2tf32(W[idx]));
    }

    int ntile = (nrows + 63) >> 6;
    for (int tile = blockIdx.x; tile < ntile; tile += gridDim.x) {
        if (t < 64) {
            int idx = tile * 64 + t;
            sRow[t] = (idx < nrows) ? idx : -1;
        }
        __syncthreads();

        // stage input rows (16 warps -> 4 rows per warp)
        for (int rr = wid; rr < 64; rr += 16) {
            int grow = sRow[rr];
            float4 acc = make_float4(0.f, 0.f, 0.f, 0.f);
            if (grow >= 0) {
                int m = grow / Nn, n = grow - m * Nn;
                const float* base = in + (size_t)m * Nn * Dd;
                acc = *(const float4*)(base + (size_t)n * Dd + lane * 4);
                if (gather) acc = gather_row(base, n, lane, acc);
            }
            float* d = &sIn[rr * SI_STR + lane * 4];
            d[0] = __uint_as_float(f2tf32(acc.x));
            d[1] = __uint_as_float(f2tf32(acc.y));
            d[2] = __uint_as_float(f2tf32(acc.z));
            d[3] = __uint_as_float(f2tf32(acc.w));
        }
        __syncthreads();

        float c_[4][4];
#pragma unroll
        for (int nt = 0; nt < 4; nt++)
#pragma unroll
            for (int q = 0; q < 4; q++) c_[nt][q] = 0.f;

#pragma unroll 4
        for (int ks = 0; ks < 16; ks++) {
            int k0 = ks * 8;
            uint32_t a[4], b[4][2];
            {
                const float* Ap = sIn + (wr * 16 + gid) * SI_STR + k0 + tig;
                a[0] = __float_as_uint(Ap[0]);
                a[1] = __float_as_uint(Ap[8 * SI_STR]);
                a[2] = __float_as_uint(Ap[4]);
                a[3] = __float_as_uint(Ap[8 * SI_STR + 4]);
            }
#pragma unroll
            for (int nt = 0; nt < 4; nt++) {
                const float* Bp = sW + (k0 + tig) * SW_STR + wc * 32 + nt * 8 + gid;
                b[nt][0] = __float_as_uint(Bp[0]);
                b[nt][1] = __float_as_uint(Bp[4 * SW_STR]);
            }
#pragma unroll
            for (int nt = 0; nt < 4; nt++)
                mma_tf32(c_[nt], a, b[nt]);
        }
        __syncthreads();

        // stage relu(acc + bias) into sIn (fp32)
#pragma unroll
        for (int nt = 0; nt < 4; nt++) {
            int col = wc * 32 + nt * 8 + tig * 2;
            int row = wr * 16 + gid;
            float b0 = bias[col], b1 = bias[col + 1];
            sIn[row * SI_STR + col]           = fmaxf(c_[nt][0] + b0, 0.f);
            sIn[row * SI_STR + col + 1]       = fmaxf(c_[nt][1] + b1, 0.f);
            sIn[(row + 8) * SI_STR + col]     = fmaxf(c_[nt][2] + b0, 0.f);
            sIn[(row + 8) * SI_STR + col + 1] = fmaxf(c_[nt][3] + b1, 0.f);
        }
        __syncthreads();

        if (pool) {
            int col = t & 127, quarter = t >> 7;   // 4 quarters x 16 rows
            float s = 0.f; int cur = -1;
            for (int rr = quarter * 16; rr < quarter * 16 + 16; rr++) {
                int grow = sRow[rr]; if (grow < 0) continue;
                int m = grow / Nn;
                int key = m * NGg + batch[grow - m * Nn];
                if (key != cur) {
                    if (cur >= 0) atomicAdd(&g_hg[(size_t)cur * Dd + col], s);
                    cur = key; s = 0.f;
                }
                s += sIn[rr * SI_STR + col];
            }
            if (cur >= 0) atomicAdd(&g_hg[(size_t)cur * Dd + col], s);
        } else {
            for (int idx = t; idx < 2048; idx += 512) {
                int rr = idx >> 5, q = idx & 31;
                int grow = sRow[rr];
                if (grow < 0) continue;
                *(float4*)(g_hB + (size_t)grow * Dd + q * 4) =
                    *(float4*)(sIn + rr * SI_STR + q * 4);
            }
        }
        __syncthreads();
    }
}

// ---------------- fused per-graph sampling ----------------
static __device__ __forceinline__ float score_fn(int n, int m, float mx, float ssum,
                                                 unsigned fk0, unsigned fk1) {
    float e = expf(g_pred[n] - mx);
    float p = e / ssum;
    float lp = logf(p + 1e-15f);
    unsigned x0 = 0u, x1 = (unsigned)(m * Nn + n);
    tf2x32(fk0, fk1, x0, x1);
    float u = __uint_as_float((x1 >> 9) | 0x3F800000u) - 1.0f;
    u = fmaxf(u, 0.0f);
    float gum = -logf(-logf(u + 1e-12f) + 1e-12f);
    return lp + gum;
}

__global__ void k_sample(const int* __restrict__ batch, unsigned fk0, unsigned fk1) {
    __shared__ float fb[8];
    __shared__ int ib[8];
    __shared__ int sSE[2];
    __shared__ float sMx, sSum, sBest;
    int g = blockIdx.x, t = threadIdx.x, lane = t & 31, wid = t >> 5;
    if (t < 2) {
        int tgt = g + t;
        int lo = 0, hi = Nn;
        while (lo < hi) { int mid = (lo + hi) >> 1; if (batch[mid] < tgt) lo = mid + 1; else hi = mid; }
        sSE[t] = lo;
    }
    __syncthreads();
    int s0 = sSE[0], s1 = sSE[1];

    float mx = -3.4e38f;
    for (int n = s0 + t; n < s1; n += 256) mx = fmaxf(mx, g_pred[n]);
#pragma unroll
    for (int o = 16; o > 0; o >>= 1) mx = fmaxf(mx, __shfl_xor_sync(0xffffffffu, mx, o));
    if (lane == 0) fb[wid] = mx;
    __syncthreads();
    if (t == 0) { float x = fb[0]; for (int i = 1; i < 8; i++) x = fmaxf(x, fb[i]); sMx = x; }
    __syncthreads();
    float gmx = sMx;

    float sm = 0.f;
    for (int n = s0 + t; n < s1; n += 256) sm += expf(g_pred[n] - gmx);
#pragma unroll
    for (int o = 16; o > 0; o >>= 1) sm += __shfl_xor_sync(0xffffffffu, sm, o);
    if (lane == 0) fb[wid] = sm;
    __syncthreads();
    if (t == 0) { float x = 0.f; for (int i = 0; i < 8; i++) x += fb[i]; sSum = x; }
    __syncthreads();
    float gsum = sSum;

    for (int m = 0; m < Mm; m++) {
        float best = -3.4e38f;
        for (int n = s0 + t; n < s1; n += 256)
            best = fmaxf(best, score_fn(n, m, gmx, gsum, fk0, fk1));
#pragma unroll
        for (int o = 16; o > 0; o >>= 1) best = fmaxf(best, __shfl_xor_sync(0xffffffffu, best, o));
        if (lane == 0) fb[wid] = best;
        __syncthreads();
        if (t == 0) { float x = fb[0]; for (int i = 1; i < 8; i++) x = fmaxf(x, fb[i]); sBest = x; }
        __syncthreads();
        float gb = sBest;
        __syncthreads();

        int cand = Nn;
        for (int n = s0 + t; n < s1; n += 256)
            if (score_fn(n, m, gmx, gsum, fk0, fk1) >= gb) cand = min(cand, n);
#pragma unroll
        for (int o = 16; o > 0; o >>= 1) cand = min(cand, __shfl_xor_sync(0xffffffffu, cand, o));
        if (lane == 0) ib[wid] = cand;
        __syncthreads();
        if (t == 0) {
            int x = ib[0]; for (int i = 1; i < 8; i++) x = min(x, ib[i]);
            if (x < Nn) {
                g_flag[m * Nn + x] = 1;
                if (atomicExch(&g_amark[m * Nn + x], 1) == 0) {
                    int p = atomicAdd(&g_naff, 1);
                    g_alist[p] = m * Nn + x;
                }
            }
        }
        __syncthreads();
    }
}

// single-pass mark: rows whose L1 aggregation changes per m
__global__ void k_mark(const int* __restrict__ esrc, const int* __restrict__ edst) {
    int e = blockIdx.x * blockDim.x + threadIdx.x;
    if (e >= Ee) return;
    int s = esrc[e];
    unsigned char f0 = g_flag[s];
    unsigned char f1 = g_flag[Nn + s];
    if (!(f0 | f1)) return;
    int d = edst[e];
    if (f0 && atomicExch(&g_amark[d], 1) == 0) {
        int p = atomicAdd(&g_naff, 1);
        g_alist[p] = d;
    }
    if (f1 && atomicExch(&g_amark[Nn + d], 1) == 0) {
        int p = atomicAdd(&g_naff, 1);
        g_alist[p] = Nn + d;
    }
}

__global__ void k_final(const float* __restrict__ Wp, const float* __restrict__ bp,
                        float* __restrict__ out) {
    __shared__ float red[128];
    int g = blockIdx.x, t = threadIdx.x;
    int c = g_counts[g]; if (c < 1) c = 1;
    float inv = 1.0f / (float)c;
    float hsum = (g_hg[(size_t)g * Dd + t] + g_hg[((size_t)NGg + g) * Dd + t]) * inv;
    for (int tt = 0; tt < 10; tt++) {
        red[t] = hsum * Wp[t * 10 + tt];
        __syncthreads();
        for (int off = 64; off > 0; off >>= 1) {
            if (t < off) red[t] += red[t + off];
            __syncthreads();
        }
        if (t == 0) out[g * 10 + tt] = red[0] * 0.5f + bp[tt];
        __syncthreads();
    }
}

// ---------------- launch ----------------
static inline int cdiv(int a, int b) { return (a + b - 1) / b; }

extern "C" void kernel_launch(void* const* d_in, const int* in_sizes, int n_in,
                              void* d_out, int out_size) {
    const int*   x_idx        = (const int*)d_in[0];
    const int*   esrc         = (const int*)d_in[1];
    const int*   edst         = (const int*)d_in[2];
    const int*   batch        = (const int*)d_in[3];
    const float* x_table      = (const float*)d_in[4];
    const float* anchor_table = (const float*)d_in[5];
    const float* Wg           = (const float*)d_in[6];
    const float* bg           = (const float*)d_in[7];
    const float* Wn           = (const float*)d_in[8];
    const float* bn           = (const float*)d_in[9];
    const float* Wd           = (const float*)d_in[10];
    const float* bd           = (const float*)d_in[11];
    const float* Wp           = (const float*)d_in[12];
    const float* bp           = (const float*)d_in[13];
    float* out = (float*)d_out;

    unsigned fk0 = 0u, fk1 = 1u;
    tf2x32(0u, 1u, fk0, fk1);

    cudaFuncSetAttribute(k_mma, cudaFuncAttributeMaxDynamicSharedMemorySize, SMEM_MMA);

    // setup
    k_reset<<<cdiv(Mm * Nn, 256), 256>>>();
    k_hist<<<cdiv(Ee, 256), 256>>>(edst);
    k_scan<<<1, 1024>>>();
    k_fill<<<cdiv(Ee, 256), 256>>>(esrc, edst);
    k_embed<<<cdiv(Nn * 32, 256), 256>>>(x_idx, x_table, batch);

    // pass1 (fp32 exact): L1 dual-write g_hA; L2 fused pred epilogue
    k_fused<<<cdiv(Nn, 64), 256>>>(0, 0, Wg, bg, nullptr, nullptr, nullptr, Nn, 0);
    k_fused<<<cdiv(Nn, 64), 256>>>(2, 1, Wg + Dd * Dd, bg + Dd, Wd, bd, nullptr, Nn, 0);

    // anchor sampling + single-pass affected-row marking
    k_sample<<<NGg, 256>>>(batch, fk0, fk1);
    k_mark<<<cdiv(Ee, 256), 256>>>(esrc, edst);

    // pass2 L1: sparse patch, virtual x' computed on the fly (fp32 exact)
    k_fused<<<148, 256>>>(1, 2, Wg, bg, nullptr, nullptr, anchor_table, 0, 1);

    // pass2 L2 (tf32 mma.sync, 512 threads): g_hA -> g_hB
    k_mma<<<148, 512, SMEM_MMA>>>(1, 0, 2, Wg + Dd * Dd, bg + Dd, batch, Mm * Nn);
    // node MLP + pooled epilogue (tf32): g_hB -> g_hg
    k_mma<<<148, 512, SMEM_MMA>>>(0, 1, 3, Wn, bn, batch, Mm * Nn);

    // final projection + mean over m
    k_final<<<NGg, 128>>>(Wp, bp, out);
}

// round 8
// speedup vs baseline: 1.6712x; 1.0584x over previous
#include <cuda_runtime.h>
#include <cstdint>

#define Nn  50000
#define Ee  800000
#define NGg 128
#define Dd  128
#define Mm  2

// ---------------- scratch ----------------
__device__ float g_tx[Nn * Dd];
__device__ float g_hA[Mm * Nn * Dd];
__device__ float g_hB[Mm * Nn * Dd];
__device__ int   g_deg[Nn];
__device__ int   g_rowptr[Nn + 1];
__device__ int   g_cursor[Nn];
__device__ int   g_col[Ee];
__device__ float g_pred[Nn];
__device__ int   g_counts[NGg];
__device__ unsigned char g_flag[Mm * Nn];
__device__ float g_hg[Mm * NGg * Dd];
__device__ int   g_amark[Mm * Nn];
__device__ int   g_alist[Mm * Nn];
__device__ int   g_naff;

// ---------------- threefry2x32 ----------------
static __host__ __device__ inline unsigned rotl32(unsigned v, int r) {
    return (v << r) | (v >> (32 - r));
}
static __host__ __device__ inline void tf2x32(unsigned k0, unsigned k1,
                                              unsigned& x0, unsigned& x1) {
    unsigned k2 = k0 ^ k1 ^ 0x1BD11BDAu;
    x0 += k0; x1 += k1;
#define TFR(r) { x0 += x1; x1 = rotl32(x1, (r)); x1 ^= x0; }
    TFR(13) TFR(15) TFR(26) TFR(6)
    x0 += k1; x1 += k2 + 1u;
    TFR(17) TFR(29) TFR(16) TFR(24)
    x0 += k2; x1 += k0 + 2u;
    TFR(13) TFR(15) TFR(26) TFR(6)
    x0 += k0; x1 += k1 + 3u;
    TFR(17) TFR(29) TFR(16) TFR(24)
    x0 += k1; x1 += k2 + 4u;
    TFR(13) TFR(15) TFR(26) TFR(6)
    x0 += k2; x1 += k0 + 5u;
#undef TFR
}

static __device__ __forceinline__ uint32_t f2tf32(float f) {
    uint32_t r;
    asm("cvt.rna.tf32.f32 %0, %1;" : "=r"(r) : "f"(f));
    return r;
}

// ---------------- gather (MLP-unrolled) ----------------
static __device__ __forceinline__ float4 gather_row(const float* __restrict__ base,
                                                    int n, int lane, float4 acc) {
    int beg = g_rowptr[n], end = g_rowptr[n + 1];
    float4 a1 = make_float4(0.f, 0.f, 0.f, 0.f);
    float4 a2 = make_float4(0.f, 0.f, 0.f, 0.f);
    float4 a3 = make_float4(0.f, 0.f, 0.f, 0.f);
    for (int b0 = beg; b0 < end; b0 += 32) {
        int lim = end - b0; if (lim > 32) lim = 32;
        int cidx = (lane < lim) ? g_col[b0 + lane] : 0;
        int j = 0;
        for (; j + 4 <= lim; j += 4) {
            int s0 = __shfl_sync(0xffffffffu, cidx, j);
            int s1 = __shfl_sync(0xffffffffu, cidx, j + 1);
            int s2 = __shfl_sync(0xffffffffu, cidx, j + 2);
            int s3 = __shfl_sync(0xffffffffu, cidx, j + 3);
            float4 v0 = *(const float4*)(base + (size_t)s0 * Dd + lane * 4);
            float4 v1 = *(const float4*)(base + (size_t)s1 * Dd + lane * 4);
            float4 v2 = *(const float4*)(base + (size_t)s2 * Dd + lane * 4);
            float4 v3 = *(const float4*)(base + (size_t)s3 * Dd + lane * 4);
            acc.x += v0.x; acc.y += v0.y; acc.z += v0.z; acc.w += v0.w;
            a1.x += v1.x; a1.y += v1.y; a1.z += v1.z; a1.w += v1.w;
            a2.x += v2.x; a2.y += v2.y; a2.z += v2.z; a2.w += v2.w;
            a3.x += v3.x; a3.y += v3.y; a3.z += v3.z; a3.w += v3.w;
        }
        for (; j < lim; j++) {
            int s0 = __shfl_sync(0xffffffffu, cidx, j);
            float4 v0 = *(const float4*)(base + (size_t)s0 * Dd + lane * 4);
            acc.x += v0.x; acc.y += v0.y; acc.z += v0.z; acc.w += v0.w;
        }
    }
    acc.x += a1.x + a2.x + a3.x;
    acc.y += a1.y + a2.y + a3.y;
    acc.z += a1.z + a2.z + a3.z;
    acc.w += a1.w + a2.w + a3.w;
    return acc;
}

// virtual x' gather: tx with flag-predicated anchor scaling (never materialized)
static __device__ __forceinline__ float4 gather_xm(int n, int lane, float4 acc,
                                                   float4 av, int m) {
    int beg = g_rowptr[n], end = g_rowptr[n + 1];
    for (int b0 = beg; b0 < end; b0 += 32) {
        int lim = end - b0; if (lim > 32) lim = 32;
        int cidx = (lane < lim) ? g_col[b0 + lane] : 0;
        for (int j = 0; j < lim; j++) {
            int s = __shfl_sync(0xffffffffu, cidx, j);
            float4 v = *(const float4*)(g_tx + (size_t)s * Dd + lane * 4);
            if (g_flag[m * Nn + s]) {
                v.x = fmaf(v.x, av.x, v.x);
                v.y = fmaf(v.y, av.y, v.y);
                v.z = fmaf(v.z, av.z, v.z);
                v.w = fmaf(v.w, av.w, v.w);
            }
            acc.x += v.x; acc.y += v.y; acc.z += v.z; acc.w += v.w;
        }
    }
    return acc;
}

// ---------------- small kernels ----------------
__global__ void k_reset() {
    int i = blockIdx.x * blockDim.x + threadIdx.x;
    if (i < Mm * Nn) { g_flag[i] = 0; g_amark[i] = 0; }
    if (i < Nn) { g_deg[i] = 0; g_cursor[i] = 0; }
    if (i < Mm * NGg * Dd) g_hg[i] = 0.f;
    if (i < NGg) g_counts[i] = 0;
    if (i == 0) g_naff = 0;
}

__global__ void k_hist(const int* __restrict__ edst) {
    int e = blockIdx.x * blockDim.x + threadIdx.x;
    if (e < Ee) atomicAdd(&g_deg[edst[e]], 1);
}

__global__ void k_scan() {
    __shared__ int ss[1024];
    int tid = threadIdx.x;
    const int CH = (Nn + 1023) / 1024;
    int beg = tid * CH;
    int end = beg + CH; if (end > Nn) end = Nn;
    int s = 0;
    for (int i = beg; i < end; i++) s += g_deg[i];
    ss[tid] = s;
    __syncthreads();
    for (int off = 1; off < 1024; off <<= 1) {
        int v = (tid >= off) ? ss[tid - off] : 0;
        __syncthreads();
        ss[tid] += v;
        __syncthreads();
    }
    int base = (tid == 0) ? 0 : ss[tid - 1];
    for (int i = beg; i < end; i++) { g_rowptr[i] = base; base += g_deg[i]; }
    if (tid == 1023) g_rowptr[Nn] = ss[1023];
}

__global__ void k_fill(const int* __restrict__ esrc, const int* __restrict__ edst) {
    int e = blockIdx.x * blockDim.x + threadIdx.x;
    if (e >= Ee) return;
    int d = edst[e];
    int p = atomicAdd(&g_cursor[d], 1);
    g_col[g_rowptr[d] + p] = esrc[e];
}

__global__ void k_embed(const int* __restrict__ x_idx, const float* __restrict__ x_table,
                        const int* __restrict__ batch) {
    int idx = blockIdx.x * blockDim.x + threadIdx.x;
    if (idx >= Nn * 32) return;
    int n = idx >> 5, q = idx & 31;
    int xi = x_idx[n];
    float4 v = *(const float4*)(x_table + (size_t)xi * Dd + q * 4);
    *(float4*)(g_tx + (size_t)n * Dd + q * 4) = v;
    if (q == 0) atomicAdd(&g_counts[batch[n]], 1);
}

// ---------------- fp32 fused gather+GEMM (pass 1 exact + sparse patch) ----------------
// insel: 0=g_tx  1=virtual x' (tx + flag scaling)  2=g_hA
// mode : 0 = relu out, dual-write both m slices of g_hA
//        1 = pred epilogue: g_pred[row] = relu(h)·Wd + bd
//        2 = relu out to g_hA (sparse patch)
__global__ __launch_bounds__(256) void k_fused(
    int insel, int mode,
    const float* __restrict__ W, const float* __restrict__ bias,
    const float* __restrict__ Wd, const float* __restrict__ bd,
    const float* __restrict__ anchor_table, int nrows, int sparse)
{
    __shared__ float sIn[64 * 129];
    __shared__ float sW[16 * 128];
    __shared__ int sRow[64];
    int t = threadIdx.x, lane = t & 31, wid = t >> 5;
    int rg = t >> 4, cg = t & 15;
    int total = sparse ? g_naff : nrows;

    for (int tile = blockIdx.x; tile * 64 < total; tile += gridDim.x) {
        if (t < 64) {
            int idx = tile * 64 + t;
            sRow[t] = (idx < total) ? (sparse ? g_alist[idx] : idx) : -1;
        }
        __syncthreads();

        for (int rr = wid; rr < 64; rr += 8) {
            int grow = sRow[rr];
            float4 acc = make_float4(0.f, 0.f, 0.f, 0.f);
            if (grow >= 0) {
                if (insel == 0) {
                    acc = *(const float4*)(g_tx + (size_t)grow * Dd + lane * 4);
                    acc = gather_row(g_tx, grow, lane, acc);
                } else if (insel == 2) {
                    acc = *(const float4*)(g_hA + (size_t)grow * Dd + lane * 4);
                    acc = gather_row(g_hA, grow, lane, acc);
                } else {
                    int m = grow / Nn, n = grow - m * Nn;
                    float4 av = *(const float4*)(anchor_table + Dd + lane * 4);
                    acc = *(const float4*)(g_tx + (size_t)n * Dd + lane * 4);
                    if (g_flag[grow]) {
                        acc.x = fmaf(acc.x, av.x, acc.x);
                        acc.y = fmaf(acc.y, av.y, acc.y);
                        acc.z = fmaf(acc.z, av.z, acc.z);
                        acc.w = fmaf(acc.w, av.w, acc.w);
                    }
                    acc = gather_xm(n, lane, acc, av, m);
                }
            }
            float* d = &sIn[rr * 129 + lane * 4];
            d[0] = acc.x; d[1] = acc.y; d[2] = acc.z; d[3] = acc.w;
        }
        __syncthreads();

        float acc[4][8];
#pragma unroll
        for (int r = 0; r < 4; r++)
#pragma unroll
            for (int j = 0; j < 8; j++) acc[r][j] = 0.f;

        for (int kc = 0; kc < 8; kc++) {
            const float4* Ws = (const float4*)(W + kc * 16 * 128);
            ((float4*)sW)[t] = Ws[t];
            ((float4*)sW)[t + 256] = Ws[t + 256];
            __syncthreads();
#pragma unroll
            for (int kk = 0; kk < 16; kk++) {
                float a[4], w[8];
#pragma unroll
                for (int r = 0; r < 4; r++) a[r] = sIn[(rg + 16 * r) * 129 + kc * 16 + kk];
#pragma unroll
                for (int j = 0; j < 8; j++) w[j] = sW[kk * 128 + cg + 16 * j];
#pragma unroll
                for (int r = 0; r < 4; r++)
#pragma unroll
                    for (int j = 0; j < 8; j++) acc[r][j] = fmaf(a[r], w[j], acc[r][j]);
            }
            __syncthreads();
        }

        if (mode == 1) {
#pragma unroll
            for (int r = 0; r < 4; r++) {
                int grow = sRow[rg + 16 * r];
                float p = 0.f;
#pragma unroll
                for (int j = 0; j < 8; j++) {
                    float v = fmaxf(acc[r][j] + bias[cg + 16 * j], 0.f);
                    p = fmaf(v, Wd[cg + 16 * j], p);
                }
#pragma unroll
                for (int o = 8; o > 0; o >>= 1) p += __shfl_xor_sync(0xffffffffu, p, o);
                if (cg == 0 && grow >= 0) g_pred[grow] = p + bd[0];
            }
        } else {
#pragma unroll
            for (int r = 0; r < 4; r++) {
                int rr = rg + 16 * r; int grow = sRow[rr];
                if (grow < 0) continue;
#pragma unroll
                for (int j = 0; j < 8; j++) {
                    float v = fmaxf(acc[r][j] + bias[cg + 16 * j], 0.f);
                    g_hA[(size_t)grow * Dd + cg + 16 * j] = v;
                    if (mode == 0) g_hA[(size_t)(grow + Nn) * Dd + cg + 16 * j] = v;
                }
            }
        }
        __syncthreads();
    }
}

// ---------------- tf32 mma.sync GEMM (R5 config: 256 thr, 2 blocks/SM) ----------------
// 64 rows x 128 cols per tile; warp grid 2x4, each warp 32 rows x 32 cols.
#define SW_STR 136
#define SI_STR 132
#define SMEM_MMA ((128 * SW_STR + 64 * SI_STR) * 4 + 64 * 4)

static __device__ __forceinline__ void mma_tf32(float* c, const uint32_t* a, const uint32_t* b) {
    asm volatile(
        "mma.sync.aligned.m16n8k8.row.col.f32.tf32.tf32.f32 "
        "{%0,%1,%2,%3}, {%4,%5,%6,%7}, {%8,%9}, {%0,%1,%2,%3};"
        : "+f"(c[0]), "+f"(c[1]), "+f"(c[2]), "+f"(c[3])
        : "r"(a[0]), "r"(a[1]), "r"(a[2]), "r"(a[3]), "r"(b[0]), "r"(b[1]));
}

__global__ __launch_bounds__(256) void k_mma(
    int gather, int pool, int insel,
    const float* __restrict__ W, const float* __restrict__ bias,
    const int* __restrict__ batch, int nrows)
{
    extern __shared__ float sm[];
    float* sW = sm;
    float* sIn = sm + 128 * SW_STR;
    int* sRow = (int*)(sIn + 64 * SI_STR);
    const float* in = (insel == 2) ? g_hA : g_hB;
    int t = threadIdx.x, lane = t & 31, wid = t >> 5;
    int gid = lane >> 2, tig = lane & 3;
    int wr = wid >> 2, wc = wid & 3;   // warp grid 2 x 4 (32 rows x 32 cols each)

    for (int idx = t; idx < 16384; idx += 256) {
        int k = idx >> 7, c = idx & 127;
        sW[k * SW_STR + c] = __uint_as_float(f2tf32(W[idx]));
    }

    int ntile = (nrows + 63) >> 6;
    for (int tile = blockIdx.x; tile < ntile; tile += gridDim.x) {
        if (t < 64) {
            int idx = tile * 64 + t;
            sRow[t] = (idx < nrows) ? idx : -1;
        }
        __syncthreads();

        for (int rr = wid; rr < 64; rr += 8) {
            int grow = sRow[rr];
            float4 acc = make_float4(0.f, 0.f, 0.f, 0.f);
            if (grow >= 0) {
                int m = grow / Nn, n = grow - m * Nn;
                const float* base = in + (size_t)m * Nn * Dd;
                acc = *(const float4*)(base + (size_t)n * Dd + lane * 4);
                if (gather) acc = gather_row(base, n, lane, acc);
            }
            float* d = &sIn[rr * SI_STR + lane * 4];
            d[0] = __uint_as_float(f2tf32(acc.x));
            d[1] = __uint_as_float(f2tf32(acc.y));
            d[2] = __uint_as_float(f2tf32(acc.z));
            d[3] = __uint_as_float(f2tf32(acc.w));
        }
        __syncthreads();

        float c_[2][4][4];
#pragma unroll
        for (int mt = 0; mt < 2; mt++)
#pragma unroll
            for (int nt = 0; nt < 4; nt++)
#pragma unroll
                for (int q = 0; q < 4; q++) c_[mt][nt][q] = 0.f;

#pragma unroll 4
        for (int ks = 0; ks < 16; ks++) {
            int k0 = ks * 8;
            uint32_t a[2][4], b[4][2];
#pragma unroll
            for (int mt = 0; mt < 2; mt++) {
                const float* Ap = sIn + (wr * 32 + mt * 16 + gid) * SI_STR + k0 + tig;
                a[mt][0] = __float_as_uint(Ap[0]);
                a[mt][1] = __float_as_uint(Ap[8 * SI_STR]);
                a[mt][2] = __float_as_uint(Ap[4]);
                a[mt][3] = __float_as_uint(Ap[8 * SI_STR + 4]);
            }
#pragma unroll
            for (int nt = 0; nt < 4; nt++) {
                const float* Bp = sW + (k0 + tig) * SW_STR + wc * 32 + nt * 8 + gid;
                b[nt][0] = __float_as_uint(Bp[0]);
                b[nt][1] = __float_as_uint(Bp[4 * SW_STR]);
            }
#pragma unroll
            for (int mt = 0; mt < 2; mt++)
#pragma unroll
                for (int nt = 0; nt < 4; nt++)
                    mma_tf32(c_[mt][nt], a[mt], b[nt]);
        }
        __syncthreads();

#pragma unroll
        for (int mt = 0; mt < 2; mt++) {
#pragma unroll
            for (int nt = 0; nt < 4; nt++) {
                int col = wc * 32 + nt * 8 + tig * 2;
                int row = wr * 32 + mt * 16 + gid;
                float b0 = bias[col], b1 = bias[col + 1];
                sIn[row * SI_STR + col]           = fmaxf(c_[mt][nt][0] + b0, 0.f);
                sIn[row * SI_STR + col + 1]       = fmaxf(c_[mt][nt][1] + b1, 0.f);
                sIn[(row + 8) * SI_STR + col]     = fmaxf(c_[mt][nt][2] + b0, 0.f);
                sIn[(row + 8) * SI_STR + col + 1] = fmaxf(c_[mt][nt][3] + b1, 0.f);
            }
        }
        __syncthreads();

        if (pool) {
            int col = t & 127, half = t >> 7;
            float s = 0.f; int cur = -1;
            for (int rr = half * 32; rr < half * 32 + 32; rr++) {
                int grow = sRow[rr]; if (grow < 0) continue;
                int m = grow / Nn;
                int key = m * NGg + batch[grow - m * Nn];
                if (key != cur) {
                    if (cur >= 0) atomicAdd(&g_hg[(size_t)cur * Dd + col], s);
                    cur = key; s = 0.f;
                }
                s += sIn[rr * SI_STR + col];
            }
            if (cur >= 0) atomicAdd(&g_hg[(size_t)cur * Dd + col], s);
        } else {
            for (int idx = t; idx < 2048; idx += 256) {
                int rr = idx >> 5, q = idx & 31;
                int grow = sRow[rr];
                if (grow < 0) continue;
                *(float4*)(g_hB + (size_t)grow * Dd + q * 4) =
                    *(float4*)(sIn + rr * SI_STR + q * 4);
            }
        }
        __syncthreads();
    }
}

// ---------------- fused per-graph sampling ----------------
static __device__ __forceinline__ float score_fn(int n, int m, float mx, float ssum,
                                                 unsigned fk0, unsigned fk1) {
    float e = expf(g_pred[n] - mx);
    float p = e / ssum;
    float lp = logf(p + 1e-15f);
    unsigned x0 = 0u, x1 = (unsigned)(m * Nn + n);
    tf2x32(fk0, fk1, x0, x1);
    float u = __uint_as_float((x1 >> 9) | 0x3F800000u) - 1.0f;
    u = fmaxf(u, 0.0f);
    float gum = -logf(-logf(u + 1e-12f) + 1e-12f);
    return lp + gum;
}

__global__ void k_sample(const int* __restrict__ batch, unsigned fk0, unsigned fk1) {
    __shared__ float fb[8];
    __shared__ int ib[8];
    __shared__ int sSE[2];
    __shared__ float sMx, sSum, sBest;
    int g = blockIdx.x, t = threadIdx.x, lane = t & 31, wid = t >> 5;
    if (t < 2) {
        int tgt = g + t;
        int lo = 0, hi = Nn;
        while (lo < hi) { int mid = (lo + hi) >> 1; if (batch[mid] < tgt) lo = mid + 1; else hi = mid; }
        sSE[t] = lo;
    }
    __syncthreads();
    int s0 = sSE[0], s1 = sSE[1];

    float mx = -3.4e38f;
    for (int n = s0 + t; n < s1; n += 256) mx = fmaxf(mx, g_pred[n]);
#pragma unroll
    for (int o = 16; o > 0; o >>= 1) mx = fmaxf(mx, __shfl_xor_sync(0xffffffffu, mx, o));
    if (lane == 0) fb[wid] = mx;
    __syncthreads();
    if (t == 0) { float x = fb[0]; for (int i = 1; i < 8; i++) x = fmaxf(x, fb[i]); sMx = x; }
    __syncthreads();
    float gmx = sMx;

    float sm = 0.f;
    for (int n = s0 + t; n < s1; n += 256) sm += expf(g_pred[n] - gmx);
#pragma unroll
    for (int o = 16; o > 0; o >>= 1) sm += __shfl_xor_sync(0xffffffffu, sm, o);
    if (lane == 0) fb[wid] = sm;
    __syncthreads();
    if (t == 0) { float x = 0.f; for (int i = 0; i < 8; i++) x += fb[i]; sSum = x; }
    __syncthreads();
    float gsum = sSum;

    for (int m = 0; m < Mm; m++) {
        float best = -3.4e38f;
        for (int n = s0 + t; n < s1; n += 256)
            best = fmaxf(best, score_fn(n, m, gmx, gsum, fk0, fk1));
#pragma unroll
        for (int o = 16; o > 0; o >>= 1) best = fmaxf(best, __shfl_xor_sync(0xffffffffu, best, o));
        if (lane == 0) fb[wid] = best;
        __syncthreads();
        if (t == 0) { float x = fb[0]; for (int i = 1; i < 8; i++) x = fmaxf(x, fb[i]); sBest = x; }
        __syncthreads();
        float gb = sBest;
        __syncthreads();

        int cand = Nn;
        for (int n = s0 + t; n < s1; n += 256)
            if (score_fn(n, m, gmx, gsum, fk0, fk1) >= gb) cand = min(cand, n);
#pragma unroll
        for (int o = 16; o > 0; o >>= 1) cand = min(cand, __shfl_xor_sync(0xffffffffu, cand, o));
        if (lane == 0) ib[wid] = cand;
        __syncthreads();
        if (t == 0) {
            int x = ib[0]; for (int i = 1; i < 8; i++) x = min(x, ib[i]);
            if (x < Nn) {
                g_flag[m * Nn + x] = 1;
                if (atomicExch(&g_amark[m * Nn + x], 1) == 0) {
                    int p = atomicAdd(&g_naff, 1);
                    g_alist[p] = m * Nn + x;
                }
            }
        }
        __syncthreads();
    }
}

// single-pass mark: rows whose L1 aggregation changes per m
__global__ void k_mark(const int* __restrict__ esrc, const int* __restrict__ edst) {
    int e = blockIdx.x * blockDim.x + threadIdx.x;
    if (e >= Ee) return;
    int s = esrc[e];
    unsigned char f0 = g_flag[s];
    unsigned char f1 = g_flag[Nn + s];
    if (!(f0 | f1)) return;
    int d = edst[e];
    if (f0 && atomicExch(&g_amark[d], 1) == 0) {
        int p = atomicAdd(&g_naff, 1);
        g_alist[p] = d;
    }
    if (f1 && atomicExch(&g_amark[Nn + d], 1) == 0) {
        int p = atomicAdd(&g_naff, 1);
        g_alist[p] = Nn + d;
    }
}

__global__ void k_final(const float* __restrict__ Wp, const float* __restrict__ bp,
                        float* __restrict__ out) {
    __shared__ float red[128];
    int g = blockIdx.x, t = threadIdx.x;
    int c = g_counts[g]; if (c < 1) c = 1;
    float inv = 1.0f / (float)c;
    float hsum = (g_hg[(size_t)g * Dd + t] + g_hg[((size_t)NGg + g) * Dd + t]) * inv;
    for (int tt = 0; tt < 10; tt++) {
        red[t] = hsum * Wp[t * 10 + tt];
        __syncthreads();
        for (int off = 64; off > 0; off >>= 1) {
            if (t < off) red[t] += red[t + off];
            __syncthreads();
        }
        if (t == 0) out[g * 10 + tt] = red[0] * 0.5f + bp[tt];
        __syncthreads();
    }
}

// ---------------- launch ----------------
static inline int cdiv(int a, int b) { return (a + b - 1) / b; }

extern "C" void kernel_launch(void* const* d_in, const int* in_sizes, int n_in,
                              void* d_out, int out_size) {
    const int*   x_idx        = (const int*)d_in[0];
    const int*   esrc         = (const int*)d_in[1];
    const int*   edst         = (const int*)d_in[2];
    const int*   batch        = (const int*)d_in[3];
    const float* x_table      = (const float*)d_in[4];
    const float* anchor_table = (const float*)d_in[5];
    const float* Wg           = (const float*)d_in[6];
    const float* bg           = (const float*)d_in[7];
    const float* Wn           = (const float*)d_in[8];
    const float* bn           = (const float*)d_in[9];
    const float* Wd           = (const float*)d_in[10];
    const float* bd           = (const float*)d_in[11];
    const float* Wp           = (const float*)d_in[12];
    const float* bp           = (const float*)d_in[13];
    float* out = (float*)d_out;

    unsigned fk0 = 0u, fk1 = 1u;
    tf2x32(0u, 1u, fk0, fk1);

    cudaFuncSetAttribute(k_mma, cudaFuncAttributeMaxDynamicSharedMemorySize, SMEM_MMA);

    // setup
    k_reset<<<cdiv(Mm * Nn, 256), 256>>>();
    k_hist<<<cdiv(Ee, 256), 256>>>(edst);
    k_scan<<<1, 1024>>>();
    k_fill<<<cdiv(Ee, 256), 256>>>(esrc, edst);
    k_embed<<<cdiv(Nn * 32, 256), 256>>>(x_idx, x_table, batch);

    // pass1 (fp32 exact): L1 dual-write g_hA; L2 fused pred epilogue
    k_fused<<<cdiv(Nn, 64), 256>>>(0, 0, Wg, bg, nullptr, nullptr, nullptr, Nn, 0);
    k_fused<<<cdiv(Nn, 64), 256>>>(2, 1, Wg + Dd * Dd, bg + Dd, Wd, bd, nullptr, Nn, 0);

    // anchor sampling + single-pass affected-row marking
    k_sample<<<NGg, 256>>>(batch, fk0, fk1);
    k_mark<<<cdiv(Ee, 256), 256>>>(esrc, edst);

    // pass2 L1: sparse patch, virtual x' computed on the fly (fp32 exact)
    k_fused<<<148, 256>>>(1, 2, Wg, bg, nullptr, nullptr, anchor_table, 0, 1);

    // pass2 L2 (tf32 mma.sync, 256 thr / 2 blocks per SM): g_hA -> g_hB
    k_mma<<<296, 256, SMEM_MMA>>>(1, 0, 2, Wg + Dd * Dd, bg + Dd, batch, Mm * Nn);
    // node MLP + pooled epilogue (tf32): g_hB -> g_hg
    k_mma<<<296, 256, SMEM_MMA>>>(0, 1, 3, Wn, bn, batch, Mm * Nn);

    // final projection + mean over m
    k_final<<<NGg, 128>>>(Wp, bp, out);
}

// round 9
// speedup vs baseline: 1.8497x; 1.1068x over previous
#include <cuda_runtime.h>
#include <cstdint>

#define Nn  50000
#define Ee  800000
#define NGg 128
#define Dd  128
#define Mm  2

// ---------------- scratch ----------------
__device__ float g_hA[Mm * Nn * Dd];
__device__ float g_hB[Mm * Nn * Dd];
__device__ int   g_deg[Nn];
__device__ int   g_rowptr[Nn + 1];
__device__ int   g_cursor[Nn];
__device__ int   g_col[Ee];
__device__ float g_pred[Nn];
__device__ int   g_counts[NGg];
__device__ unsigned char g_flag[Mm * Nn];
__device__ float g_hg[Mm * NGg * Dd];
__device__ int   g_amark[Mm * Nn];
__device__ int   g_alist[Mm * Nn];
__device__ int   g_naff;

// ---------------- threefry2x32 ----------------
static __host__ __device__ inline unsigned rotl32(unsigned v, int r) {
    return (v << r) | (v >> (32 - r));
}
static __host__ __device__ inline void tf2x32(unsigned k0, unsigned k1,
                                              unsigned& x0, unsigned& x1) {
    unsigned k2 = k0 ^ k1 ^ 0x1BD11BDAu;
    x0 += k0; x1 += k1;
#define TFR(r) { x0 += x1; x1 = rotl32(x1, (r)); x1 ^= x0; }
    TFR(13) TFR(15) TFR(26) TFR(6)
    x0 += k1; x1 += k2 + 1u;
    TFR(17) TFR(29) TFR(16) TFR(24)
    x0 += k2; x1 += k0 + 2u;
    TFR(13) TFR(15) TFR(26) TFR(6)
    x0 += k0; x1 += k1 + 3u;
    TFR(17) TFR(29) TFR(16) TFR(24)
    x0 += k1; x1 += k2 + 4u;
    TFR(13) TFR(15) TFR(26) TFR(6)
    x0 += k2; x1 += k0 + 5u;
#undef TFR
}

static __device__ __forceinline__ uint32_t f2tf32(float f) {
    uint32_t r;
    asm("cvt.rna.tf32.f32 %0, %1;" : "=r"(r) : "f"(f));
    return r;
}

// ---------------- gather from a dense fp32 matrix (MLP-unrolled) ----------------
static __device__ __forceinline__ float4 gather_row(const float* __restrict__ base,
                                                    int n, int lane, float4 acc) {
    int beg = g_rowptr[n], end = g_rowptr[n + 1];
    float4 a1 = make_float4(0.f, 0.f, 0.f, 0.f);
    float4 a2 = make_float4(0.f, 0.f, 0.f, 0.f);
    float4 a3 = make_float4(0.f, 0.f, 0.f, 0.f);
    for (int b0 = beg; b0 < end; b0 += 32) {
        int lim = end - b0; if (lim > 32) lim = 32;
        int cidx = (lane < lim) ? g_col[b0 + lane] : 0;
        int j = 0;
        for (; j + 4 <= lim; j += 4) {
            int s0 = __shfl_sync(0xffffffffu, cidx, j);
            int s1 = __shfl_sync(0xffffffffu, cidx, j + 1);
            int s2 = __shfl_sync(0xffffffffu, cidx, j + 2);
            int s3 = __shfl_sync(0xffffffffu, cidx, j + 3);
            float4 v0 = *(const float4*)(base + (size_t)s0 * Dd + lane * 4);
            float4 v1 = *(const float4*)(base + (size_t)s1 * Dd + lane * 4);
            float4 v2 = *(const float4*)(base + (size_t)s2 * Dd + lane * 4);
            float4 v3 = *(const float4*)(base + (size_t)s3 * Dd + lane * 4);
            acc.x += v0.x; acc.y += v0.y; acc.z += v0.z; acc.w += v0.w;
            a1.x += v1.x; a1.y += v1.y; a1.z += v1.z; a1.w += v1.w;
            a2.x += v2.x; a2.y += v2.y; a2.z += v2.z; a2.w += v2.w;
            a3.x += v3.x; a3.y += v3.y; a3.z += v3.z; a3.w += v3.w;
        }
        for (; j < lim; j++) {
            int s0 = __shfl_sync(0xffffffffu, cidx, j);
            float4 v0 = *(const float4*)(base + (size_t)s0 * Dd + lane * 4);
            acc.x += v0.x; acc.y += v0.y; acc.z += v0.z; acc.w += v0.w;
        }
    }
    acc.x += a1.x + a2.x + a3.x;
    acc.y += a1.y + a2.y + a3.y;
    acc.z += a1.z + a2.z + a3.z;
    acc.w += a1.w + a2.w + a3.w;
    return acc;
}

// gather tx from smem vocab table: per edge only a 4B x_idx load from global
static __device__ __forceinline__ float4 gather_tx(const float* __restrict__ sXT,
                                                   const int* __restrict__ x_idx,
                                                   int n, int lane, float4 acc) {
    int beg = g_rowptr[n], end = g_rowptr[n + 1];
    float4 a1 = make_float4(0.f, 0.f, 0.f, 0.f);
    float4 a2 = make_float4(0.f, 0.f, 0.f, 0.f);
    float4 a3 = make_float4(0.f, 0.f, 0.f, 0.f);
    for (int b0 = beg; b0 < end; b0 += 32) {
        int lim = end - b0; if (lim > 32) lim = 32;
        int xv = 0;
        if (lane < lim) xv = x_idx[g_col[b0 + lane]];
        int j = 0;
        for (; j + 4 <= lim; j += 4) {
            int s0 = __shfl_sync(0xffffffffu, xv, j);
            int s1 = __shfl_sync(0xffffffffu, xv, j + 1);
            int s2 = __shfl_sync(0xffffffffu, xv, j + 2);
            int s3 = __shfl_sync(0xffffffffu, xv, j + 3);
            float4 v0 = *(const float4*)(sXT + s0 * Dd + lane * 4);
            float4 v1 = *(const float4*)(sXT + s1 * Dd + lane * 4);
            float4 v2 = *(const float4*)(sXT + s2 * Dd + lane * 4);
            float4 v3 = *(const float4*)(sXT + s3 * Dd + lane * 4);
            acc.x += v0.x; acc.y += v0.y; acc.z += v0.z; acc.w += v0.w;
            a1.x += v1.x; a1.y += v1.y; a1.z += v1.z; a1.w += v1.w;
            a2.x += v2.x; a2.y += v2.y; a2.z += v2.z; a2.w += v2.w;
            a3.x += v3.x; a3.y += v3.y; a3.z += v3.z; a3.w += v3.w;
        }
        for (; j < lim; j++) {
            int s0 = __shfl_sync(0xffffffffu, xv, j);
            float4 v0 = *(const float4*)(sXT + s0 * Dd + lane * 4);
            acc.x += v0.x; acc.y += v0.y; acc.z += v0.z; acc.w += v0.w;
        }
    }
    acc.x += a1.x + a2.x + a3.x;
    acc.y += a1.y + a2.y + a3.y;
    acc.z += a1.z + a2.z + a3.z;
    acc.w += a1.w + a2.w + a3.w;
    return acc;
}

// virtual x' gather: smem vocab row + flag-predicated anchor scaling (sparse patch)
static __device__ __forceinline__ float4 gather_xm(const float* __restrict__ sXT,
                                                   const int* __restrict__ x_idx,
                                                   int n, int lane, float4 acc,
                                                   float4 av, int m) {
    int beg = g_rowptr[n], end = g_rowptr[n + 1];
    for (int b0 = beg; b0 < end; b0 += 32) {
        int lim = end - b0; if (lim > 32) lim = 32;
        int pk = 0;
        if (lane < lim) {
            int s = g_col[b0 + lane];
            pk = x_idx[s] | ((int)g_flag[m * Nn + s] << 8);
        }
        for (int j = 0; j < lim; j++) {
            int p = __shfl_sync(0xffffffffu, pk, j);
            float4 v = *(const float4*)(sXT + (p & 255) * Dd + lane * 4);
            if (p >> 8) {
                v.x = fmaf(v.x, av.x, v.x);
                v.y = fmaf(v.y, av.y, v.y);
                v.z = fmaf(v.z, av.z, v.z);
                v.w = fmaf(v.w, av.w, v.w);
            }
            acc.x += v.x; acc.y += v.y; acc.z += v.z; acc.w += v.w;
        }
    }
    return acc;
}

// ---------------- small kernels ----------------
__global__ void k_reset() {
    int i = blockIdx.x * blockDim.x + threadIdx.x;
    if (i < Mm * Nn) { g_flag[i] = 0; g_amark[i] = 0; }
    if (i < Nn) { g_deg[i] = 0; g_cursor[i] = 0; }
    if (i < Mm * NGg * Dd) g_hg[i] = 0.f;
    if (i < NGg) g_counts[i] = 0;
    if (i == 0) g_naff = 0;
}

__global__ void k_hist(const int* __restrict__ edst) {
    int e = blockIdx.x * blockDim.x + threadIdx.x;
    if (e < Ee) atomicAdd(&g_deg[edst[e]], 1);
}

__global__ void k_counts(const int* __restrict__ batch) {
    int n = blockIdx.x * blockDim.x + threadIdx.x;
    if (n < Nn) atomicAdd(&g_counts[batch[n]], 1);
}

__global__ void k_scan() {
    __shared__ int ss[1024];
    int tid = threadIdx.x;
    const int CH = (Nn + 1023) / 1024;
    int beg = tid * CH;
    int end = beg + CH; if (end > Nn) end = Nn;
    int s = 0;
    for (int i = beg; i < end; i++) s += g_deg[i];
    ss[tid] = s;
    __syncthreads();
    for (int off = 1; off < 1024; off <<= 1) {
        int v = (tid >= off) ? ss[tid - off] : 0;
        __syncthreads();
        ss[tid] += v;
        __syncthreads();
    }
    int base = (tid == 0) ? 0 : ss[tid - 1];
    for (int i = beg; i < end; i++) { g_rowptr[i] = base; base += g_deg[i]; }
    if (tid == 1023) g_rowptr[Nn] = ss[1023];
}

__global__ void k_fill(const int* __restrict__ esrc, const int* __restrict__ edst) {
    int e = blockIdx.x * blockDim.x + threadIdx.x;
    if (e >= Ee) return;
    int d = edst[e];
    int p = atomicAdd(&g_cursor[d], 1);
    g_col[g_rowptr[d] + p] = esrc[e];
}

// ---------------- fp32 fused gather+GEMM (pass 1 exact + sparse patch) ----------------
// insel: 0 = tx from smem vocab table (pass1 L1)
//        1 = virtual x' from smem vocab table (sparse patch)
//        2 = g_hA (pass1 L2)
// mode : 0 = relu out, dual-write both m slices of g_hA
//        1 = pred epilogue: g_pred[row] = relu(h)·Wd + bd
//        2 = relu out to g_hA (sparse patch)
// dynamic smem: sIn[64*129] | sRow[64] | sU[4096 floats if insel<2 else 2048]
#define SM_FUSED_XT ((64 * 129 + 64 + 32 * 128) * 4)
#define SM_FUSED_H  ((64 * 129 + 64 + 16 * 128) * 4)
__global__ __launch_bounds__(256) void k_fused(
    int insel, int mode,
    const float* __restrict__ W, const float* __restrict__ bias,
    const float* __restrict__ Wd, const float* __restrict__ bd,
    const float* __restrict__ anchor_table,
    const int* __restrict__ x_idx, const float* __restrict__ x_table,
    int nrows, int sparse)
{
    extern __shared__ float sm[];
    float* sIn = sm;                       // 64*129
    int*   sRow = (int*)(sIn + 64 * 129);  // 64
    float* sU = (float*)(sRow + 64);       // vocab table (staging) / W chunk (GEMM)
    int t = threadIdx.x, lane = t & 31, wid = t >> 5;
    int rg = t >> 4, cg = t & 15;
    int total = sparse ? g_naff : nrows;

    for (int tile = blockIdx.x; tile * 64 < total; tile += gridDim.x) {
        if (t < 64) {
            int idx = tile * 64 + t;
            sRow[t] = (idx < total) ? (sparse ? g_alist[idx] : idx) : -1;
        }
        if (insel < 2) {
            // (re)load the 16KB vocab table (L1-hot after the first tile)
            const float4* xt4 = (const float4*)x_table;
            float4* s4 = (float4*)sU;
            for (int i = t; i < 1024; i += 256) s4[i] = xt4[i];
        }
        __syncthreads();

        for (int rr = wid; rr < 64; rr += 8) {
            int grow = sRow[rr];
            float4 acc = make_float4(0.f, 0.f, 0.f, 0.f);
            if (grow >= 0) {
                if (insel == 0) {
                    int xi = x_idx[grow];
                    acc = *(const float4*)(sU + xi * Dd + lane * 4);
                    acc = gather_tx(sU, x_idx, grow, lane, acc);
                } else if (insel == 2) {
                    acc = *(const float4*)(g_hA + (size_t)grow * Dd + lane * 4);
                    acc = gather_row(g_hA, grow, lane, acc);
                } else {
                    int m = grow / Nn, n = grow - m * Nn;
                    float4 av = *(const float4*)(anchor_table + Dd + lane * 4);
                    int xi = x_idx[n];
                    acc = *(const float4*)(sU + xi * Dd + lane * 4);
                    if (g_flag[grow]) {
                        acc.x = fmaf(acc.x, av.x, acc.x);
                        acc.y = fmaf(acc.y, av.y, acc.y);
                        acc.z = fmaf(acc.z, av.z, acc.z);
                        acc.w = fmaf(acc.w, av.w, acc.w);
                    }
                    acc = gather_xm(sU, x_idx, n, lane, acc, av, m);
                }
            }
            float* d = &sIn[rr * 129 + lane * 4];
            d[0] = acc.x; d[1] = acc.y; d[2] = acc.z; d[3] = acc.w;
        }
        __syncthreads();

        float acc[4][8];
#pragma unroll
        for (int r = 0; r < 4; r++)
#pragma unroll
            for (int j = 0; j < 8; j++) acc[r][j] = 0.f;

        for (int kc = 0; kc < 8; kc++) {
            const float4* Ws = (const float4*)(W + kc * 16 * 128);
            ((float4*)sU)[t] = Ws[t];
            ((float4*)sU)[t + 256] = Ws[t + 256];
            __syncthreads();
#pragma unroll
            for (int kk = 0; kk < 16; kk++) {
                float a[4], w[8];
#pragma unroll
                for (int r = 0; r < 4; r++) a[r] = sIn[(rg + 16 * r) * 129 + kc * 16 + kk];
#pragma unroll
                for (int j = 0; j < 8; j++) w[j] = sU[kk * 128 + cg + 16 * j];
#pragma unroll
                for (int r = 0; r < 4; r++)
#pragma unroll
                    for (int j = 0; j < 8; j++) acc[r][j] = fmaf(a[r], w[j], acc[r][j]);
            }
            __syncthreads();
        }

        if (mode == 1) {
#pragma unroll
            for (int r = 0; r < 4; r++) {
                int grow = sRow[rg + 16 * r];
                float p = 0.f;
#pragma unroll
                for (int j = 0; j < 8; j++) {
                    float v = fmaxf(acc[r][j] + bias[cg + 16 * j], 0.f);
                    p = fmaf(v, Wd[cg + 16 * j], p);
                }
#pragma unroll
                for (int o = 8; o > 0; o >>= 1) p += __shfl_xor_sync(0xffffffffu, p, o);
                if (cg == 0 && grow >= 0) g_pred[grow] = p + bd[0];
            }
        } else {
#pragma unroll
            for (int r = 0; r < 4; r++) {
                int rr = rg + 16 * r; int grow = sRow[rr];
                if (grow < 0) continue;
#pragma unroll
                for (int j = 0; j < 8; j++) {
                    float v = fmaxf(acc[r][j] + bias[cg + 16 * j], 0.f);
                    g_hA[(size_t)grow * Dd + cg + 16 * j] = v;
                    if (mode == 0) g_hA[(size_t)(grow + Nn) * Dd + cg + 16 * j] = v;
                }
            }
        }
        __syncthreads();
    }
}

// ---------------- tf32 mma.sync GEMM (256 thr, 2 blocks/SM) ----------------
#define SW_STR 136
#define SI_STR 132
#define SMEM_MMA ((128 * SW_STR + 64 * SI_STR) * 4 + 64 * 4)

static __device__ __forceinline__ void mma_tf32(float* c, const uint32_t* a, const uint32_t* b) {
    asm volatile(
        "mma.sync.aligned.m16n8k8.row.col.f32.tf32.tf32.f32 "
        "{%0,%1,%2,%3}, {%4,%5,%6,%7}, {%8,%9}, {%0,%1,%2,%3};"
        : "+f"(c[0]), "+f"(c[1]), "+f"(c[2]), "+f"(c[3])
        : "r"(a[0]), "r"(a[1]), "r"(a[2]), "r"(a[3]), "r"(b[0]), "r"(b[1]));
}

__global__ __launch_bounds__(256) void k_mma(
    int gather, int pool, int insel,
    const float* __restrict__ W, const float* __restrict__ bias,
    const int* __restrict__ batch, int nrows)
{
    extern __shared__ float sm[];
    float* sW = sm;
    float* sIn = sm + 128 * SW_STR;
    int* sRow = (int*)(sIn + 64 * SI_STR);
    const float* in = (insel == 2) ? g_hA : g_hB;
    int t = threadIdx.x, lane = t & 31, wid = t >> 5;
    int gid = lane >> 2, tig = lane & 3;
    int wr = wid >> 2, wc = wid & 3;

    for (int idx = t; idx < 16384; idx += 256) {
        int k = idx >> 7, c = idx & 127;
        sW[k * SW_STR + c] = __uint_as_float(f2tf32(W[idx]));
    }

    int ntile = (nrows + 63) >> 6;
    for (int tile = blockIdx.x; tile < ntile; tile += gridDim.x) {
        if (t < 64) {
            int idx = tile * 64 + t;
            sRow[t] = (idx < nrows) ? idx : -1;
        }
        __syncthreads();

        for (int rr = wid; rr < 64; rr += 8) {
            int grow = sRow[rr];
            float4 acc = make_float4(0.f, 0.f, 0.f, 0.f);
            if (grow >= 0) {
                int m = grow / Nn, n = grow - m * Nn;
                const float* base = in + (size_t)m * Nn * Dd;
                acc = *(const float4*)(base + (size_t)n * Dd + lane * 4);
                if (gather) acc = gather_row(base, n, lane, acc);
            }
            float* d = &sIn[rr * SI_STR + lane * 4];
            d[0] = __uint_as_float(f2tf32(acc.x));
            d[1] = __uint_as_float(f2tf32(acc.y));
            d[2] = __uint_as_float(f2tf32(acc.z));
            d[3] = __uint_as_float(f2tf32(acc.w));
        }
        __syncthreads();

        float c_[2][4][4];
#pragma unroll
        for (int mt = 0; mt < 2; mt++)
#pragma unroll
            for (int nt = 0; nt < 4; nt++)
#pragma unroll
                for (int q = 0; q < 4; q++) c_[mt][nt][q] = 0.f;

#pragma unroll 4
        for (int ks = 0; ks < 16; ks++) {
            int k0 = ks * 8;
            uint32_t a[2][4], b[4][2];
#pragma unroll
            for (int mt = 0; mt < 2; mt++) {
                const float* Ap = sIn + (wr * 32 + mt * 16 + gid) * SI_STR + k0 + tig;
                a[mt][0] = __float_as_uint(Ap[0]);
                a[mt][1] = __float_as_uint(Ap[8 * SI_STR]);
                a[mt][2] = __float_as_uint(Ap[4]);
                a[mt][3] = __float_as_uint(Ap[8 * SI_STR + 4]);
            }
#pragma unroll
            for (int nt = 0; nt < 4; nt++) {
                const float* Bp = sW + (k0 + tig) * SW_STR + wc * 32 + nt * 8 + gid;
                b[nt][0] = __float_as_uint(Bp[0]);
                b[nt][1] = __float_as_uint(Bp[4 * SW_STR]);
            }
#pragma unroll
            for (int mt = 0; mt < 2; mt++)
#pragma unroll
                for (int nt = 0; nt < 4; nt++)
                    mma_tf32(c_[mt][nt], a[mt], b[nt]);
        }
        __syncthreads();

#pragma unroll
        for (int mt = 0; mt < 2; mt++) {
#pragma unroll
            for (int nt = 0; nt < 4; nt++) {
                int col = wc * 32 + nt * 8 + tig * 2;
                int row = wr * 32 + mt * 16 + gid;
                float b0 = bias[col], b1 = bias[col + 1];
                sIn[row * SI_STR + col]           = fmaxf(c_[mt][nt][0] + b0, 0.f);
                sIn[row * SI_STR + col + 1]       = fmaxf(c_[mt][nt][1] + b1, 0.f);
                sIn[(row + 8) * SI_STR + col]     = fmaxf(c_[mt][nt][2] + b0, 0.f);
                sIn[(row + 8) * SI_STR + col + 1] = fmaxf(c_[mt][nt][3] + b1, 0.f);
            }
        }
        __syncthreads();

        if (pool) {
            int col = t & 127, half = t >> 7;
            float s = 0.f; int cur = -1;
            for (int rr = half * 32; rr < half * 32 + 32; rr++) {
                int grow = sRow[rr]; if (grow < 0) continue;
                int m = grow / Nn;
                int key = m * NGg + batch[grow - m * Nn];
                if (key != cur) {
                    if (cur >= 0) atomicAdd(&g_hg[(size_t)cur * Dd + col], s);
                    cur = key; s = 0.f;
                }
                s += sIn[rr * SI_STR + col];
            }
            if (cur >= 0) atomicAdd(&g_hg[(size_t)cur * Dd + col], s);
        } else {
            for (int idx = t; idx < 2048; idx += 256) {
                int rr = idx >> 5, q = idx & 31;
                int grow = sRow[rr];
                if (grow < 0) continue;
                *(float4*)(g_hB + (size_t)grow * Dd + q * 4) =
                    *(float4*)(sIn + rr * SI_STR + q * 4);
            }
        }
        __syncthreads();
    }
}

// ---------------- fused per-graph sampling ----------------
static __device__ __forceinline__ float score_fn(int n, int m, float mx, float ssum,
                                                 unsigned fk0, unsigned fk1) {
    float e = expf(g_pred[n] - mx);
    float p = e / ssum;
    float lp = logf(p + 1e-15f);
    unsigned x0 = 0u, x1 = (unsigned)(m * Nn + n);
    tf2x32(fk0, fk1, x0, x1);
    float u = __uint_as_float((x1 >> 9) | 0x3F800000u) - 1.0f;
    u = fmaxf(u, 0.0f);
    float gum = -logf(-logf(u + 1e-12f) + 1e-12f);
    return lp + gum;
}

__global__ void k_sample(const int* __restrict__ batch, unsigned fk0, unsigned fk1) {
    __shared__ float fb[8];
    __shared__ int ib[8];
    __shared__ int sSE[2];
    __shared__ float sMx, sSum, sBest;
    int g = blockIdx.x, t = threadIdx.x, lane = t & 31, wid = t >> 5;
    if (t < 2) {
        int tgt = g + t;
        int lo = 0, hi = Nn;
        while (lo < hi) { int mid = (lo + hi) >> 1; if (batch[mid] < tgt) lo = mid + 1; else hi = mid; }
        sSE[t] = lo;
    }
    __syncthreads();
    int s0 = sSE[0], s1 = sSE[1];

    float mx = -3.4e38f;
    for (int n = s0 + t; n < s1; n += 256) mx = fmaxf(mx, g_pred[n]);
#pragma unroll
    for (int o = 16; o > 0; o >>= 1) mx = fmaxf(mx, __shfl_xor_sync(0xffffffffu, mx, o));
    if (lane == 0) fb[wid] = mx;
    __syncthreads();
    if (t == 0) { float x = fb[0]; for (int i = 1; i < 8; i++) x = fmaxf(x, fb[i]); sMx = x; }
    __syncthreads();
    float gmx = sMx;

    float sm = 0.f;
    for (int n = s0 + t; n < s1; n += 256) sm += expf(g_pred[n] - gmx);
#pragma unroll
    for (int o = 16; o > 0; o >>= 1) sm += __shfl_xor_sync(0xffffffffu, sm, o);
    if (lane == 0) fb[wid] = sm;
    __syncthreads();
    if (t == 0) { float x = 0.f; for (int i = 0; i < 8; i++) x += fb[i]; sSum = x; }
    __syncthreads();
    float gsum = sSum;

    for (int m = 0; m < Mm; m++) {
        float best = -3.4e38f;
        for (int n = s0 + t; n < s1; n += 256)
            best = fmaxf(best, score_fn(n, m, gmx, gsum, fk0, fk1));
#pragma unroll
        for (int o = 16; o > 0; o >>= 1) best = fmaxf(best, __shfl_xor_sync(0xffffffffu, best, o));
        if (lane == 0) fb[wid] = best;
        __syncthreads();
        if (t == 0) { float x = fb[0]; for (int i = 1; i < 8; i++) x = fmaxf(x, fb[i]); sBest = x; }
        __syncthreads();
        float gb = sBest;
        __syncthreads();

        int cand = Nn;
        for (int n = s0 + t; n < s1; n += 256)
            if (score_fn(n, m, gmx, gsum, fk0, fk1) >= gb) cand = min(cand, n);
#pragma unroll
        for (int o = 16; o > 0; o >>= 1) cand = min(cand, __shfl_xor_sync(0xffffffffu, cand, o));
        if (lane == 0) ib[wid] = cand;
        __syncthreads();
        if (t == 0) {
            int x = ib[0]; for (int i = 1; i < 8; i++) x = min(x, ib[i]);
            if (x < Nn) {
                g_flag[m * Nn + x] = 1;
                if (atomicExch(&g_amark[m * Nn + x], 1) == 0) {
                    int p = atomicAdd(&g_naff, 1);
                    g_alist[p] = m * Nn + x;
                }
            }
        }
        __syncthreads();
    }
}

// single-pass mark: rows whose L1 aggregation changes per m
__global__ void k_mark(const int* __restrict__ esrc, const int* __restrict__ edst) {
    int e = blockIdx.x * blockDim.x + threadIdx.x;
    if (e >= Ee) return;
    int s = esrc[e];
    unsigned char f0 = g_flag[s];
    unsigned char f1 = g_flag[Nn + s];
    if (!(f0 | f1)) return;
    int d = edst[e];
    if (f0 && atomicExch(&g_amark[d], 1) == 0) {
        int p = atomicAdd(&g_naff, 1);
        g_alist[p] = d;
    }
    if (f1 && atomicExch(&g_amark[Nn + d], 1) == 0) {
        int p = atomicAdd(&g_naff, 1);
        g_alist[p] = Nn + d;
    }
}

__global__ void k_final(const float* __restrict__ Wp, const float* __restrict__ bp,
                        float* __restrict__ out) {
    __shared__ float red[128];
    int g = blockIdx.x, t = threadIdx.x;
    int c = g_counts[g]; if (c < 1) c = 1;
    float inv = 1.0f / (float)c;
    float hsum = (g_hg[(size_t)g * Dd + t] + g_hg[((size_t)NGg + g) * Dd + t]) * inv;
    for (int tt = 0; tt < 10; tt++) {
        red[t] = hsum * Wp[t * 10 + tt];
        __syncthreads();
        for (int off = 64; off > 0; off >>= 1) {
            if (t < off) red[t] += red[t + off];
            __syncthreads();
        }
        if (t == 0) out[g * 10 + tt] = red[0] * 0.5f + bp[tt];
        __syncthreads();
    }
}

// ---------------- launch ----------------
static inline int cdiv(int a, int b) { return (a + b - 1) / b; }

extern "C" void kernel_launch(void* const* d_in, const int* in_sizes, int n_in,
                              void* d_out, int out_size) {
    const int*   x_idx        = (const int*)d_in[0];
    const int*   esrc         = (const int*)d_in[1];
    const int*   edst         = (const int*)d_in[2];
    const int*   batch        = (const int*)d_in[3];
    const float* x_table      = (const float*)d_in[4];
    const float* anchor_table = (const float*)d_in[5];
    const float* Wg           = (const float*)d_in[6];
    const float* bg           = (const float*)d_in[7];
    const float* Wn           = (const float*)d_in[8];
    const float* bn           = (const float*)d_in[9];
    const float* Wd           = (const float*)d_in[10];
    const float* bd           = (const float*)d_in[11];
    const float* Wp           = (const float*)d_in[12];
    const float* bp           = (const float*)d_in[13];
    float* out = (float*)d_out;

    unsigned fk0 = 0u, fk1 = 1u;
    tf2x32(0u, 1u, fk0, fk1);

    cudaFuncSetAttribute(k_mma, cudaFuncAttributeMaxDynamicSharedMemorySize, SMEM_MMA);
    cudaFuncSetAttribute(k_fused, cudaFuncAttributeMaxDynamicSharedMemorySize, SM_FUSED_XT);

    // setup (no tx materialization — vocab table stays in smem/L1)
    k_reset<<<cdiv(Mm * Nn, 256), 256>>>();
    k_hist<<<cdiv(Ee, 256), 256>>>(edst);
    k_scan<<<1, 1024>>>();
    k_fill<<<cdiv(Ee, 256), 256>>>(esrc, edst);
    k_counts<<<cdiv(Nn, 256), 256>>>(batch);

    // pass1 (fp32 exact): L1 from smem vocab table, dual-write g_hA; L2 fused pred
    k_fused<<<cdiv(Nn, 64), 256, SM_FUSED_XT>>>(0, 0, Wg, bg, nullptr, nullptr,
                                                nullptr, x_idx, x_table, Nn, 0);
    k_fused<<<cdiv(Nn, 64), 256, SM_FUSED_H>>>(2, 1, Wg + Dd * Dd, bg + Dd, Wd, bd,
                                               nullptr, x_idx, x_table, Nn, 0);

    // anchor sampling + single-pass affected-row marking
    k_sample<<<NGg, 256>>>(batch, fk0, fk1);
    k_mark<<<cdiv(Ee, 256), 256>>>(esrc, edst);

    // pass2 L1: sparse patch, virtual x' from smem vocab table (fp32 exact)
    k_fused<<<148, 256, SM_FUSED_XT>>>(1, 2, Wg, bg, nullptr, nullptr,
                                       anchor_table, x_idx, x_table, 0, 1);

    // pass2 L2 (tf32 mma.sync): g_hA -> g_hB
    k_mma<<<296, 256, SMEM_MMA>>>(1, 0, 2, Wg + Dd * Dd, bg + Dd, batch, Mm * Nn);
    // node MLP + pooled epilogue (tf32): g_hB -> g_hg
    k_mma<<<296, 256, SMEM_MMA>>>(0, 1, 3, Wn, bn, batch, Mm * Nn);

    // final projection + mean over m
    k_final<<<NGg, 128>>>(Wp, bp, out);
}